// round 2
// baseline (speedup 1.0000x reference)
#include <cuda_runtime.h>
#include <math.h>

#define HID   2048
#define DOWND 512
#define NE    16
#define NTOK  8192
#define NPAIR (NTOK*2)

#define BM 128
#define BN 128
#define BK 8

// ---------------- scratch (static device memory; no allocs allowed) ----------------
__device__ float g_eo[NPAIR*DOWND];     // per-(token,expert-slot) scaled expert output
__device__ float g_h [NTOK*DOWND];      // gelu(combined)
__device__ int   g_pair_tok[NPAIR];
__device__ float g_pair_w [NPAIR];
__device__ int   g_tok_pair[NTOK*2];
__device__ int   g_ei[NTOK*2];
__device__ float g_wp[NTOK*2];
__device__ int   g_cnt[NE];
__device__ int   g_off[NE];
__device__ int   g_cur[NE];
__device__ float g_sum[NE];

typedef unsigned long long ull;

__device__ __forceinline__ ull pk2(float x, float y){
    ull r; asm("mov.b64 %0,{%1,%2};" : "=l"(r) : "f"(x), "f"(y)); return r;
}
__device__ __forceinline__ void upk2(ull v, float &x, float &y){
    asm("mov.b64 {%0,%1},%2;" : "=f"(x), "=f"(y) : "l"(v));
}
// packed fp32x2 FMA (Blackwell): d = a*b + d, two fp32 lanes per instruction
__device__ __forceinline__ void fma2(ull &d, ull a, ull b){
    asm("fma.rn.f32x2 %0,%1,%2,%0;" : "+l"(d) : "l"(a), "l"(b));
}

__device__ __forceinline__ float gelu_new(float v){
    float c = v + 0.044715f * v * v * v;
    return 0.5f * v * (1.0f + tanhf(0.7978845608028654f * c));
}

// ---------------- kernels ----------------

__global__ void k_init(){
    int t = threadIdx.x;
    if (t < NE){ g_cnt[t] = 0; g_sum[t] = 0.0f; }
}

// warp per token: 16 dots of length 2048, top-2, softmax, routing + loss sums
__global__ void k_gate(const float* __restrict__ x, const float* __restrict__ gw){
    int w    = threadIdx.x >> 5;
    int lane = threadIdx.x & 31;
    int n = blockIdx.x * 8 + w;
    const float4* xr = (const float4*)(x + (size_t)n * HID);
    const float4* g4 = (const float4*)gw;
    float acc[NE];
#pragma unroll
    for (int e = 0; e < NE; e++) acc[e] = 0.0f;
    for (int i = 0; i < 16; i++){
        float4 xv = xr[lane + 32*i];
#pragma unroll
        for (int e = 0; e < NE; e++){
            float4 gv = g4[e*(HID/4) + lane + 32*i];
            acc[e] += xv.x*gv.x + xv.y*gv.y + xv.z*gv.z + xv.w*gv.w;
        }
    }
#pragma unroll
    for (int e = 0; e < NE; e++){
#pragma unroll
        for (int o = 16; o > 0; o >>= 1)
            acc[e] += __shfl_xor_sync(0xffffffffu, acc[e], o);
    }
    if (lane == 0){
        float v0 = -1e30f, v1 = -1e30f; int i0 = 0, i1 = 0;
#pragma unroll
        for (int e = 0; e < NE; e++){
            float v = acc[e];
            if (v > v0){ v1 = v0; i1 = i0; v0 = v; i0 = e; }
            else if (v > v1){ v1 = v; i1 = e; }
        }
        float ee = expf(v1 - v0);
        float s  = 1.0f + ee;
        float w0 = 1.0f / s, w1 = ee / s;
        g_ei[2*n]   = i0; g_ei[2*n+1] = i1;
        g_wp[2*n]   = w0; g_wp[2*n+1] = w1;
        atomicAdd(&g_cnt[i0], 1);  atomicAdd(&g_cnt[i1], 1);
        atomicAdd(&g_sum[i0], w0); atomicAdd(&g_sum[i1], w1);
    }
}

__global__ void k_prefix(float* __restrict__ loss_out){
    if (threadIdx.x == 0 && blockIdx.x == 0){
        int a = 0; float ls = 0.0f;
        for (int e = 0; e < NE; e++){
            g_off[e] = a; g_cur[e] = a; a += g_cnt[e];
            float t = g_sum[e] / (float)NTOK;
            ls += t * t;
        }
        *loss_out = (float)NE * ls * 0.1f;
    }
}

__global__ void k_scatter(){
    int n = blockIdx.x * blockDim.x + threadIdx.x;
    if (n >= NTOK) return;
#pragma unroll
    for (int s = 0; s < 2; s++){
        int e = g_ei[2*n+s];
        int p = atomicAdd(&g_cur[e], 1);
        g_pair_tok[p] = n;
        g_pair_w [p]  = g_wp[2*n+s];
        g_tok_pair[2*n+s] = p;
    }
}

// grouped expert GEMM: for expert e, C[pair, down] = (X_gather · W_e^T + b_e) * w_pair
__global__ void __launch_bounds__(256, 2)
k_expert(const float* __restrict__ x, const float* __restrict__ dw,
         const float* __restrict__ db){
    int e   = blockIdx.z;
    int cnt = g_cnt[e];
    int m0  = blockIdx.x * BM;
    if (m0 >= cnt) return;
    int base = g_off[e];
    int n0   = blockIdx.y * BN;
    const float* W = dw + (size_t)e * DOWND * HID;

    __shared__ float As[BK][BM+4];
    __shared__ float Bs[BK][BN+4];

    int tid = threadIdx.x;
    int lr = tid >> 1;          // load row 0..127
    int lk = (tid & 1) * 4;     // 0 or 4

    int am = m0 + lr;
    int tok = (am < cnt) ? g_pair_tok[base + am] : 0;
    const float* arow = x + (size_t)tok * HID;
    const float* brow = W + (size_t)(n0 + lr) * HID;

    int tx = tid & 15, ty = tid >> 4;
    int mo = ty * 8, no = tx * 8;

    ull acc[8][4];
#pragma unroll
    for (int i = 0; i < 8; i++)
#pragma unroll
        for (int j = 0; j < 4; j++) acc[i][j] = 0ull;

    for (int kt = 0; kt < HID; kt += BK){
        float4 av = *(const float4*)(arow + kt + lk);
        float4 bv = *(const float4*)(brow + kt + lk);
        __syncthreads();
        As[lk+0][lr] = av.x; As[lk+1][lr] = av.y; As[lk+2][lr] = av.z; As[lk+3][lr] = av.w;
        Bs[lk+0][lr] = bv.x; Bs[lk+1][lr] = bv.y; Bs[lk+2][lr] = bv.z; Bs[lk+3][lr] = bv.w;
        __syncthreads();
#pragma unroll
        for (int k = 0; k < BK; k++){
            float ar[8], br[8];
            *(float4*)&ar[0] = *(const float4*)&As[k][mo];
            *(float4*)&ar[4] = *(const float4*)&As[k][mo+4];
            *(float4*)&br[0] = *(const float4*)&Bs[k][no];
            *(float4*)&br[4] = *(const float4*)&Bs[k][no+4];
            ull bb[4];
            bb[0] = pk2(br[0], br[1]); bb[1] = pk2(br[2], br[3]);
            bb[2] = pk2(br[4], br[5]); bb[3] = pk2(br[6], br[7]);
#pragma unroll
            for (int i = 0; i < 8; i++){
                ull aa = pk2(ar[i], ar[i]);
#pragma unroll
                for (int j = 0; j < 4; j++) fma2(acc[i][j], aa, bb[j]);
            }
        }
    }

    float bias[8];
#pragma unroll
    for (int j = 0; j < 8; j++) bias[j] = db[e*DOWND + n0 + no + j];
#pragma unroll
    for (int i = 0; i < 8; i++){
        int m = m0 + mo + i;
        if (m < cnt){
            int p = base + m;
            float w = g_pair_w[p];
            float r[8];
#pragma unroll
            for (int j = 0; j < 4; j++) upk2(acc[i][j], r[2*j], r[2*j+1]);
            float4 o0, o1;
            o0.x = (r[0]+bias[0])*w; o0.y = (r[1]+bias[1])*w;
            o0.z = (r[2]+bias[2])*w; o0.w = (r[3]+bias[3])*w;
            o1.x = (r[4]+bias[4])*w; o1.y = (r[5]+bias[5])*w;
            o1.z = (r[6]+bias[6])*w; o1.w = (r[7]+bias[7])*w;
            *(float4*)&g_eo[(size_t)p*DOWND + n0 + no    ] = o0;
            *(float4*)&g_eo[(size_t)p*DOWND + n0 + no + 4] = o1;
        }
    }
}

// h[n] = gelu(eo[pair0] + eo[pair1])
__global__ void k_combine(){
    int idx = blockIdx.x * blockDim.x + threadIdx.x;   // over NTOK*DOWND/4
    int n = idx >> 7;          // DOWND/4 = 128 float4 per token
    int d = idx & 127;
    int p0 = g_tok_pair[2*n], p1 = g_tok_pair[2*n+1];
    float4 v0 = *(const float4*)&g_eo[(size_t)p0*DOWND + 4*d];
    float4 v1 = *(const float4*)&g_eo[(size_t)p1*DOWND + 4*d];
    float4 o;
    o.x = gelu_new(v0.x + v1.x);
    o.y = gelu_new(v0.y + v1.y);
    o.z = gelu_new(v0.z + v1.z);
    o.w = gelu_new(v0.w + v1.w);
    *(float4*)&g_h[(size_t)n*DOWND + 4*d] = o;
}

// out[n, o] = h[n] · up_w[o]^T + up_b[o]
__global__ void __launch_bounds__(256, 2)
k_up(const float* __restrict__ uw, const float* __restrict__ ub,
     float* __restrict__ out){
    int m0 = blockIdx.x * BM;
    int n0 = blockIdx.y * BN;

    __shared__ float As[BK][BM+4];
    __shared__ float Bs[BK][BN+4];

    int tid = threadIdx.x;
    int lr = tid >> 1;
    int lk = (tid & 1) * 4;
    const float* arow = g_h + (size_t)(m0 + lr) * DOWND;
    const float* brow = uw  + (size_t)(n0 + lr) * DOWND;

    int tx = tid & 15, ty = tid >> 4;
    int mo = ty * 8, no = tx * 8;

    ull acc[8][4];
#pragma unroll
    for (int i = 0; i < 8; i++)
#pragma unroll
        for (int j = 0; j < 4; j++) acc[i][j] = 0ull;

    for (int kt = 0; kt < DOWND; kt += BK){
        float4 av = *(const float4*)(arow + kt + lk);
        float4 bv = *(const float4*)(brow + kt + lk);
        __syncthreads();
        As[lk+0][lr] = av.x; As[lk+1][lr] = av.y; As[lk+2][lr] = av.z; As[lk+3][lr] = av.w;
        Bs[lk+0][lr] = bv.x; Bs[lk+1][lr] = bv.y; Bs[lk+2][lr] = bv.z; Bs[lk+3][lr] = bv.w;
        __syncthreads();
#pragma unroll
        for (int k = 0; k < BK; k++){
            float ar[8], br[8];
            *(float4*)&ar[0] = *(const float4*)&As[k][mo];
            *(float4*)&ar[4] = *(const float4*)&As[k][mo+4];
            *(float4*)&br[0] = *(const float4*)&Bs[k][no];
            *(float4*)&br[4] = *(const float4*)&Bs[k][no+4];
            ull bb[4];
            bb[0] = pk2(br[0], br[1]); bb[1] = pk2(br[2], br[3]);
            bb[2] = pk2(br[4], br[5]); bb[3] = pk2(br[6], br[7]);
#pragma unroll
            for (int i = 0; i < 8; i++){
                ull aa = pk2(ar[i], ar[i]);
#pragma unroll
                for (int j = 0; j < 4; j++) fma2(acc[i][j], aa, bb[j]);
            }
        }
    }

    float bias[8];
#pragma unroll
    for (int j = 0; j < 8; j++) bias[j] = ub[n0 + no + j];
#pragma unroll
    for (int i = 0; i < 8; i++){
        int m = m0 + mo + i;
        float r[8];
#pragma unroll
        for (int j = 0; j < 4; j++) upk2(acc[i][j], r[2*j], r[2*j+1]);
        float4 o0, o1;
        o0.x = r[0]+bias[0]; o0.y = r[1]+bias[1]; o0.z = r[2]+bias[2]; o0.w = r[3]+bias[3];
        o1.x = r[4]+bias[4]; o1.y = r[5]+bias[5]; o1.z = r[6]+bias[6]; o1.w = r[7]+bias[7];
        *(float4*)&out[(size_t)m*HID + n0 + no    ] = o0;
        *(float4*)&out[(size_t)m*HID + n0 + no + 4] = o1;
    }
}

// ---------------- launch ----------------
extern "C" void kernel_launch(void* const* d_in, const int* in_sizes, int n_in,
                              void* d_out, int out_size){
    const float* x      = (const float*)d_in[0];
    const float* gate_w = (const float*)d_in[1];
    const float* down_w = (const float*)d_in[2];
    const float* down_b = (const float*)d_in[3];
    const float* up_w   = (const float*)d_in[4];
    const float* up_b   = (const float*)d_in[5];
    float* out = (float*)d_out;

    k_init<<<1, 32>>>();
    k_gate<<<NTOK/8, 256>>>(x, gate_w);
    k_prefix<<<1, 1>>>(out + (size_t)NTOK * HID);   // loss scalar after the [B,S,HIDDEN] block
    k_scatter<<<NTOK/256, 256>>>();

    dim3 ge(64, DOWND/BN, NE);                      // 64 m-tiles covers worst-case routing skew
    k_expert<<<ge, 256>>>(x, down_w, down_b);

    k_combine<<<(NTOK*DOWND/4)/256, 256>>>();

    dim3 gu(NTOK/BM, HID/BN);
    k_up<<<gu, 256>>>(up_w, up_b, out);
}

// round 3
// speedup vs baseline: 1.0015x; 1.0015x over previous
#include <cuda_runtime.h>
#include <math.h>

#define HID   2048
#define DOWND 512
#define NE    16
#define NTOK  8192
#define NPAIR (NTOK*2)

#define BM 128
#define BN 128
#define BK 8

// ---------------- scratch (static device memory; no allocs allowed) ----------------
__device__ float g_eo[NPAIR*DOWND];     // per-(token,expert-slot) scaled expert output
__device__ float g_h [NTOK*DOWND];      // gelu(combined)
__device__ int   g_pair_tok[NPAIR];
__device__ float g_pair_w [NPAIR];
__device__ int   g_tok_pair[NTOK*2];
__device__ int   g_ei[NTOK*2];
__device__ float g_wp[NTOK*2];
__device__ int   g_cnt[NE];
__device__ int   g_off[NE];
__device__ int   g_cur[NE];
__device__ float g_sum[NE];

typedef unsigned long long ull;

__device__ __forceinline__ ull pk2(float x, float y){
    ull r; asm("mov.b64 %0,{%1,%2};" : "=l"(r) : "f"(x), "f"(y)); return r;
}
__device__ __forceinline__ void upk2(ull v, float &x, float &y){
    asm("mov.b64 {%0,%1},%2;" : "=f"(x), "=f"(y) : "l"(v));
}
// packed fp32x2 FMA (Blackwell): d = a*b + d, two fp32 lanes per instruction
__device__ __forceinline__ void fma2(ull &d, ull a, ull b){
    asm("fma.rn.f32x2 %0,%1,%2,%0;" : "+l"(d) : "l"(a), "l"(b));
}

__device__ __forceinline__ float gelu_new(float v){
    float c = v + 0.044715f * v * v * v;
    return 0.5f * v * (1.0f + tanhf(0.7978845608028654f * c));
}

// ---------------- kernels ----------------

__global__ void k_init(){
    int t = threadIdx.x;
    if (t < NE){ g_cnt[t] = 0; g_sum[t] = 0.0f; }
}

// warp per token: 16 dots of length 2048, top-2, softmax, routing + loss sums
__global__ void k_gate(const float* __restrict__ x, const float* __restrict__ gw){
    int w    = threadIdx.x >> 5;
    int lane = threadIdx.x & 31;
    int n = blockIdx.x * 8 + w;
    const float4* xr = (const float4*)(x + (size_t)n * HID);
    const float4* g4 = (const float4*)gw;
    float acc[NE];
#pragma unroll
    for (int e = 0; e < NE; e++) acc[e] = 0.0f;
    for (int i = 0; i < 16; i++){
        float4 xv = xr[lane + 32*i];
#pragma unroll
        for (int e = 0; e < NE; e++){
            float4 gv = g4[e*(HID/4) + lane + 32*i];
            acc[e] += xv.x*gv.x + xv.y*gv.y + xv.z*gv.z + xv.w*gv.w;
        }
    }
#pragma unroll
    for (int e = 0; e < NE; e++){
#pragma unroll
        for (int o = 16; o > 0; o >>= 1)
            acc[e] += __shfl_xor_sync(0xffffffffu, acc[e], o);
    }
    if (lane == 0){
        float v0 = -1e30f, v1 = -1e30f; int i0 = 0, i1 = 0;
#pragma unroll
        for (int e = 0; e < NE; e++){
            float v = acc[e];
            if (v > v0){ v1 = v0; i1 = i0; v0 = v; i0 = e; }
            else if (v > v1){ v1 = v; i1 = e; }
        }
        float ee = expf(v1 - v0);
        float s  = 1.0f + ee;
        float w0 = 1.0f / s, w1 = ee / s;
        g_ei[2*n]   = i0; g_ei[2*n+1] = i1;
        g_wp[2*n]   = w0; g_wp[2*n+1] = w1;
        atomicAdd(&g_cnt[i0], 1);  atomicAdd(&g_cnt[i1], 1);
        atomicAdd(&g_sum[i0], w0); atomicAdd(&g_sum[i1], w1);
    }
}

__global__ void k_prefix(float* __restrict__ loss_out){
    if (threadIdx.x == 0 && blockIdx.x == 0){
        int a = 0; float ls = 0.0f;
        for (int e = 0; e < NE; e++){
            g_off[e] = a; g_cur[e] = a; a += g_cnt[e];
            float t = g_sum[e] / (float)NTOK;
            ls += t * t;
        }
        *loss_out = (float)NE * ls * 0.1f;
    }
}

__global__ void k_scatter(){
    int n = blockIdx.x * blockDim.x + threadIdx.x;
    if (n >= NTOK) return;
#pragma unroll
    for (int s = 0; s < 2; s++){
        int e = g_ei[2*n+s];
        int p = atomicAdd(&g_cur[e], 1);
        g_pair_tok[p] = n;
        g_pair_w [p]  = g_wp[2*n+s];
        g_tok_pair[2*n+s] = p;
    }
}

// grouped expert GEMM: for expert e, C[pair, down] = (X_gather · W_e^T + b_e) * w_pair
__global__ void __launch_bounds__(256, 2)
k_expert(const float* __restrict__ x, const float* __restrict__ dw,
         const float* __restrict__ db){
    int e   = blockIdx.z;
    int cnt = g_cnt[e];
    int m0  = blockIdx.x * BM;
    if (m0 >= cnt) return;
    int base = g_off[e];
    int n0   = blockIdx.y * BN;
    const float* W = dw + (size_t)e * DOWND * HID;

    __shared__ float As[BK][BM+4];
    __shared__ float Bs[BK][BN+4];

    int tid = threadIdx.x;
    int lr = tid >> 1;          // load row 0..127
    int lk = (tid & 1) * 4;     // 0 or 4

    int am = m0 + lr;
    int tok = (am < cnt) ? g_pair_tok[base + am] : 0;
    const float* arow = x + (size_t)tok * HID;
    const float* brow = W + (size_t)(n0 + lr) * HID;

    int tx = tid & 15, ty = tid >> 4;
    int mo = ty * 8, no = tx * 8;

    ull acc[8][4];
#pragma unroll
    for (int i = 0; i < 8; i++)
#pragma unroll
        for (int j = 0; j < 4; j++) acc[i][j] = 0ull;

    for (int kt = 0; kt < HID; kt += BK){
        float4 av = *(const float4*)(arow + kt + lk);
        float4 bv = *(const float4*)(brow + kt + lk);
        __syncthreads();
        As[lk+0][lr] = av.x; As[lk+1][lr] = av.y; As[lk+2][lr] = av.z; As[lk+3][lr] = av.w;
        Bs[lk+0][lr] = bv.x; Bs[lk+1][lr] = bv.y; Bs[lk+2][lr] = bv.z; Bs[lk+3][lr] = bv.w;
        __syncthreads();
#pragma unroll
        for (int k = 0; k < BK; k++){
            float ar[8], br[8];
            *(float4*)&ar[0] = *(const float4*)&As[k][mo];
            *(float4*)&ar[4] = *(const float4*)&As[k][mo+4];
            *(float4*)&br[0] = *(const float4*)&Bs[k][no];
            *(float4*)&br[4] = *(const float4*)&Bs[k][no+4];
            ull bb[4];
            bb[0] = pk2(br[0], br[1]); bb[1] = pk2(br[2], br[3]);
            bb[2] = pk2(br[4], br[5]); bb[3] = pk2(br[6], br[7]);
#pragma unroll
            for (int i = 0; i < 8; i++){
                ull aa = pk2(ar[i], ar[i]);
#pragma unroll
                for (int j = 0; j < 4; j++) fma2(acc[i][j], aa, bb[j]);
            }
        }
    }

    float bias[8];
#pragma unroll
    for (int j = 0; j < 8; j++) bias[j] = db[e*DOWND + n0 + no + j];
#pragma unroll
    for (int i = 0; i < 8; i++){
        int m = m0 + mo + i;
        if (m < cnt){
            int p = base + m;
            float w = g_pair_w[p];
            float r[8];
#pragma unroll
            for (int j = 0; j < 4; j++) upk2(acc[i][j], r[2*j], r[2*j+1]);
            float4 o0, o1;
            o0.x = (r[0]+bias[0])*w; o0.y = (r[1]+bias[1])*w;
            o0.z = (r[2]+bias[2])*w; o0.w = (r[3]+bias[3])*w;
            o1.x = (r[4]+bias[4])*w; o1.y = (r[5]+bias[5])*w;
            o1.z = (r[6]+bias[6])*w; o1.w = (r[7]+bias[7])*w;
            *(float4*)&g_eo[(size_t)p*DOWND + n0 + no    ] = o0;
            *(float4*)&g_eo[(size_t)p*DOWND + n0 + no + 4] = o1;
        }
    }
}

// h[n] = gelu(eo[pair0] + eo[pair1])
__global__ void k_combine(){
    int idx = blockIdx.x * blockDim.x + threadIdx.x;   // over NTOK*DOWND/4
    int n = idx >> 7;          // DOWND/4 = 128 float4 per token
    int d = idx & 127;
    int p0 = g_tok_pair[2*n], p1 = g_tok_pair[2*n+1];
    float4 v0 = *(const float4*)&g_eo[(size_t)p0*DOWND + 4*d];
    float4 v1 = *(const float4*)&g_eo[(size_t)p1*DOWND + 4*d];
    float4 o;
    o.x = gelu_new(v0.x + v1.x);
    o.y = gelu_new(v0.y + v1.y);
    o.z = gelu_new(v0.z + v1.z);
    o.w = gelu_new(v0.w + v1.w);
    *(float4*)&g_h[(size_t)n*DOWND + 4*d] = o;
}

// out[n, o] = h[n] · up_w[o]^T + up_b[o]
__global__ void __launch_bounds__(256, 2)
k_up(const float* __restrict__ uw, const float* __restrict__ ub,
     float* __restrict__ out){
    int m0 = blockIdx.x * BM;
    int n0 = blockIdx.y * BN;

    __shared__ float As[BK][BM+4];
    __shared__ float Bs[BK][BN+4];

    int tid = threadIdx.x;
    int lr = tid >> 1;
    int lk = (tid & 1) * 4;
    const float* arow = g_h + (size_t)(m0 + lr) * DOWND;
    const float* brow = uw  + (size_t)(n0 + lr) * DOWND;

    int tx = tid & 15, ty = tid >> 4;
    int mo = ty * 8, no = tx * 8;

    ull acc[8][4];
#pragma unroll
    for (int i = 0; i < 8; i++)
#pragma unroll
        for (int j = 0; j < 4; j++) acc[i][j] = 0ull;

    for (int kt = 0; kt < DOWND; kt += BK){
        float4 av = *(const float4*)(arow + kt + lk);
        float4 bv = *(const float4*)(brow + kt + lk);
        __syncthreads();
        As[lk+0][lr] = av.x; As[lk+1][lr] = av.y; As[lk+2][lr] = av.z; As[lk+3][lr] = av.w;
        Bs[lk+0][lr] = bv.x; Bs[lk+1][lr] = bv.y; Bs[lk+2][lr] = bv.z; Bs[lk+3][lr] = bv.w;
        __syncthreads();
#pragma unroll
        for (int k = 0; k < BK; k++){
            float ar[8], br[8];
            *(float4*)&ar[0] = *(const float4*)&As[k][mo];
            *(float4*)&ar[4] = *(const float4*)&As[k][mo+4];
            *(float4*)&br[0] = *(const float4*)&Bs[k][no];
            *(float4*)&br[4] = *(const float4*)&Bs[k][no+4];
            ull bb[4];
            bb[0] = pk2(br[0], br[1]); bb[1] = pk2(br[2], br[3]);
            bb[2] = pk2(br[4], br[5]); bb[3] = pk2(br[6], br[7]);
#pragma unroll
            for (int i = 0; i < 8; i++){
                ull aa = pk2(ar[i], ar[i]);
#pragma unroll
                for (int j = 0; j < 4; j++) fma2(acc[i][j], aa, bb[j]);
            }
        }
    }

    float bias[8];
#pragma unroll
    for (int j = 0; j < 8; j++) bias[j] = ub[n0 + no + j];
#pragma unroll
    for (int i = 0; i < 8; i++){
        int m = m0 + mo + i;
        float r[8];
#pragma unroll
        for (int j = 0; j < 4; j++) upk2(acc[i][j], r[2*j], r[2*j+1]);
        float4 o0, o1;
        o0.x = r[0]+bias[0]; o0.y = r[1]+bias[1]; o0.z = r[2]+bias[2]; o0.w = r[3]+bias[3];
        o1.x = r[4]+bias[4]; o1.y = r[5]+bias[5]; o1.z = r[6]+bias[6]; o1.w = r[7]+bias[7];
        *(float4*)&out[(size_t)m*HID + n0 + no    ] = o0;
        *(float4*)&out[(size_t)m*HID + n0 + no + 4] = o1;
    }
}

// ---------------- launch ----------------
extern "C" void kernel_launch(void* const* d_in, const int* in_sizes, int n_in,
                              void* d_out, int out_size){
    const float* x      = (const float*)d_in[0];
    const float* gate_w = (const float*)d_in[1];
    const float* down_w = (const float*)d_in[2];
    const float* down_b = (const float*)d_in[3];
    const float* up_w   = (const float*)d_in[4];
    const float* up_b   = (const float*)d_in[5];
    float* out = (float*)d_out;

    k_init<<<1, 32>>>();
    k_gate<<<NTOK/8, 256>>>(x, gate_w);
    k_prefix<<<1, 1>>>(out + (size_t)NTOK * HID);   // loss scalar after the [B,S,HIDDEN] block
    k_scatter<<<NTOK/256, 256>>>();

    dim3 ge(64, DOWND/BN, NE);                      // 64 m-tiles covers worst-case routing skew
    k_expert<<<ge, 256>>>(x, down_w, down_b);

    k_combine<<<(NTOK*DOWND/4)/256, 256>>>();

    dim3 gu(NTOK/BM, HID/BN);
    k_up<<<gu, 256>>>(up_w, up_b, out);
}

// round 6
// speedup vs baseline: 2.5461x; 2.5423x over previous
#include <cuda_runtime.h>
#include <cuda_bf16.h>
#include <math.h>
#include <stdint.h>

#define HID   2048
#define DOWND 512
#define NE    16
#define NTOK  8192
#define NPAIR (NTOK*2)

// ---------------- scratch (static device memory; no allocs allowed) ----------------
__device__ float g_eo[NPAIR*DOWND];          // scaled expert outputs (fp32)
__device__ __nv_bfloat16 g_xh[NTOK*HID];     // x split hi/lo
__device__ __nv_bfloat16 g_xl[NTOK*HID];
__device__ __nv_bfloat16 g_wh[NE*DOWND*HID]; // down_w split hi/lo
__device__ __nv_bfloat16 g_wl[NE*DOWND*HID];
__device__ __nv_bfloat16 g_uh[HID*DOWND];    // up_w split hi/lo
__device__ __nv_bfloat16 g_ul[HID*DOWND];
__device__ __nv_bfloat16 g_hh[NTOK*DOWND];   // gelu(combined) split hi/lo
__device__ __nv_bfloat16 g_hl[NTOK*DOWND];
__device__ int   g_pair_tok[NPAIR];
__device__ float g_pair_w [NPAIR];
__device__ int   g_tok_pair[NTOK*2];
__device__ int   g_ei[NTOK*2];
__device__ float g_wp[NTOK*2];
__device__ int   g_cnt[NE];
__device__ int   g_off[NE];
__device__ int   g_cur[NE];
__device__ float g_sum[NE];

// ---------------- PTX helpers (Ampere-class: valid on compute_103 base) ----------------
__device__ __forceinline__ uint32_t smem_u32(const void* p){
    uint32_t a;
    asm("{ .reg .u64 t; cvta.to.shared.u64 t, %1; cvt.u32.u64 %0, t; }" : "=r"(a) : "l"(p));
    return a;
}
__device__ __forceinline__ void cpa16(uint32_t saddr, const void* g){
    asm volatile("cp.async.cg.shared.global [%0], [%1], 16;" :: "r"(saddr), "l"(g));
}
__device__ __forceinline__ void ldm_x4(uint32_t* r, uint32_t addr){
    asm volatile("ldmatrix.sync.aligned.m8n8.x4.shared.b16 {%0,%1,%2,%3}, [%4];"
        : "=r"(r[0]), "=r"(r[1]), "=r"(r[2]), "=r"(r[3]) : "r"(addr));
}
__device__ __forceinline__ void ldm_x2(uint32_t* r, uint32_t addr){
    asm volatile("ldmatrix.sync.aligned.m8n8.x2.shared.b16 {%0,%1}, [%2];"
        : "=r"(r[0]), "=r"(r[1]) : "r"(addr));
}
__device__ __forceinline__ void mma16816(float* c, const uint32_t* a, const uint32_t* b){
    asm volatile("mma.sync.aligned.m16n8k16.row.col.f32.bf16.bf16.f32 "
        "{%0,%1,%2,%3}, {%4,%5,%6,%7}, {%8,%9}, {%0,%1,%2,%3};"
        : "+f"(c[0]), "+f"(c[1]), "+f"(c[2]), "+f"(c[3])
        : "r"(a[0]), "r"(a[1]), "r"(a[2]), "r"(a[3]), "r"(b[0]), "r"(b[1]));
}

__device__ __forceinline__ float gelu_new(float v){
    float c = v + 0.044715f * v * v * v;
    return 0.5f * v * (1.0f + tanhf(0.7978845608028654f * c));
}

// ---------------- routing kernels ----------------
__global__ void k_init(){
    int t = threadIdx.x;
    if (t < NE){ g_cnt[t] = 0; g_sum[t] = 0.0f; }
}

__global__ void k_gate(const float* __restrict__ x, const float* __restrict__ gw){
    int w    = threadIdx.x >> 5;
    int lane = threadIdx.x & 31;
    int n = blockIdx.x * 8 + w;
    const float4* xr = (const float4*)(x + (size_t)n * HID);
    const float4* g4 = (const float4*)gw;
    float acc[NE];
#pragma unroll
    for (int e = 0; e < NE; e++) acc[e] = 0.0f;
    for (int i = 0; i < 16; i++){
        float4 xv = xr[lane + 32*i];
#pragma unroll
        for (int e = 0; e < NE; e++){
            float4 gv = g4[e*(HID/4) + lane + 32*i];
            acc[e] += xv.x*gv.x + xv.y*gv.y + xv.z*gv.z + xv.w*gv.w;
        }
    }
#pragma unroll
    for (int e = 0; e < NE; e++){
#pragma unroll
        for (int o = 16; o > 0; o >>= 1)
            acc[e] += __shfl_xor_sync(0xffffffffu, acc[e], o);
    }
    if (lane == 0){
        float v0 = -1e30f, v1 = -1e30f; int i0 = 0, i1 = 0;
#pragma unroll
        for (int e = 0; e < NE; e++){
            float v = acc[e];
            if (v > v0){ v1 = v0; i1 = i0; v0 = v; i0 = e; }
            else if (v > v1){ v1 = v; i1 = e; }
        }
        float ee = expf(v1 - v0);
        float s  = 1.0f + ee;
        float w0 = 1.0f / s, w1 = ee / s;
        g_ei[2*n]   = i0; g_ei[2*n+1] = i1;
        g_wp[2*n]   = w0; g_wp[2*n+1] = w1;
        atomicAdd(&g_cnt[i0], 1);  atomicAdd(&g_cnt[i1], 1);
        atomicAdd(&g_sum[i0], w0); atomicAdd(&g_sum[i1], w1);
    }
}

__global__ void k_prefix(float* __restrict__ loss_out){
    if (threadIdx.x == 0 && blockIdx.x == 0){
        int a = 0; float ls = 0.0f;
        for (int e = 0; e < NE; e++){
            g_off[e] = a; g_cur[e] = a; a += g_cnt[e];
            float t = g_sum[e] / (float)NTOK;
            ls += t * t;
        }
        *loss_out = (float)NE * ls * 0.1f;
    }
}

__global__ void k_scatter(){
    int n = blockIdx.x * blockDim.x + threadIdx.x;
    if (n >= NTOK) return;
#pragma unroll
    for (int s = 0; s < 2; s++){
        int e = g_ei[2*n+s];
        int p = atomicAdd(&g_cur[e], 1);
        g_pair_tok[p] = n;
        g_pair_w [p]  = g_wp[2*n+s];
        g_tok_pair[2*n+s] = p;
    }
}

// ---------------- fp32 -> bf16 hi/lo split conversion ----------------
__global__ void k_cvt(const float* __restrict__ in, __nv_bfloat16* __restrict__ h,
                      __nv_bfloat16* __restrict__ l, int n4){
    int i = blockIdx.x * blockDim.x + threadIdx.x;
    if (i >= n4) return;
    float4 v = ((const float4*)in)[i];
    __nv_bfloat16 h0 = __float2bfloat16(v.x);
    __nv_bfloat16 h1 = __float2bfloat16(v.y);
    __nv_bfloat16 h2 = __float2bfloat16(v.z);
    __nv_bfloat16 h3 = __float2bfloat16(v.w);
    __nv_bfloat16 l0 = __float2bfloat16(v.x - __bfloat162float(h0));
    __nv_bfloat16 l1 = __float2bfloat16(v.y - __bfloat162float(h1));
    __nv_bfloat16 l2 = __float2bfloat16(v.z - __bfloat162float(h2));
    __nv_bfloat16 l3 = __float2bfloat16(v.w - __bfloat162float(h3));
    __nv_bfloat162* hp = (__nv_bfloat162*)h;
    __nv_bfloat162* lp = (__nv_bfloat162*)l;
    hp[2*i]   = __nv_bfloat162(h0, h1);
    hp[2*i+1] = __nv_bfloat162(h2, h3);
    lp[2*i]   = __nv_bfloat162(l0, l1);
    lp[2*i+1] = __nv_bfloat162(l2, l3);
}

// ---------------- warp-MMA GEMM (bf16 3-term split, fp32 accum) ----------------
// Tiles: block 128x128, BK=64 bf16, 8 warps (2x4), warp tile 64x32.
// SMEM stage: Ah/Al/Bh/Bl each 128 rows x 128B (XOR swizzled) = 64KB; 3 stages.
#define STAGE_BYTES 65536
#define OFF_AH 0
#define OFF_AL 16384
#define OFF_BH 32768
#define OFF_BL 49152
#define GSMEM  (3*STAGE_BYTES)

template<bool EXPERT, int KDIM>
__global__ void __launch_bounds__(256)
k_gemm(const __nv_bfloat16* __restrict__ Ah, const __nv_bfloat16* __restrict__ Al,
       const __nv_bfloat16* __restrict__ Bh, const __nv_bfloat16* __restrict__ Bl,
       const float* __restrict__ bias, float* __restrict__ C)
{
    int e   = EXPERT ? blockIdx.z : 0;
    int cnt = EXPERT ? g_cnt[e] : NTOK;
    int m0  = blockIdx.x * 128;
    if (m0 >= cnt) return;
    int base = EXPERT ? g_off[e] : 0;
    int n0   = blockIdx.y * 128;
    const float* bptr = EXPERT ? bias + e*DOWND : bias;

    extern __shared__ char smem[];
    uint32_t sm = smem_u32(smem);
    __shared__ int s_aoff[128];
    __shared__ int s_boff[128];

    int tid  = threadIdx.x;
    int lane = tid & 31;
    int wid  = tid >> 5;
    int wm   = wid >> 2;      // 0..1
    int wn   = wid & 3;       // 0..3

    if (tid < 128){
        int m = m0 + tid;
        int ar;
        if (EXPERT) ar = g_pair_tok[base + ((m < cnt) ? m : 0)];
        else        ar = m;
        s_aoff[tid] = ar * KDIM;
        int bn = (EXPERT ? e*DOWND : 0) + n0 + tid;
        s_boff[tid] = bn * KDIM;
    }
    __syncthreads();

    const int NK = KDIM / 64;

    auto copy_stage = [&](int kt, int buf){
        uint32_t st = sm + buf*STAGE_BYTES;
        int kbase = kt*64;
#pragma unroll
        for (int i = 0; i < 4; i++){
            int idx = tid + i*256;         // 0..1023
            int row = idx >> 3;
            int c   = idx & 7;
            uint32_t soff = (uint32_t)row*128u + (uint32_t)(((c ^ (row & 7)) & 7)*16);
            int ga = s_aoff[row] + kbase + c*8;
            int gb = s_boff[row] + kbase + c*8;
            cpa16(st + OFF_AH + soff, Ah + ga);
            cpa16(st + OFF_AL + soff, Al + ga);
            cpa16(st + OFF_BH + soff, Bh + gb);
            cpa16(st + OFF_BL + soff, Bl + gb);
        }
    };

    // prologue: up to 3 stages, one commit per real copy (no empty groups)
    copy_stage(0, 0);
    asm volatile("cp.async.commit_group;" ::: "memory");
    if (NK > 1){ copy_stage(1, 1); asm volatile("cp.async.commit_group;" ::: "memory"); }
    if (NK > 2){ copy_stage(2, 2); asm volatile("cp.async.commit_group;" ::: "memory"); }

    float acc[4][4][4];
#pragma unroll
    for (int a = 0; a < 4; a++)
#pragma unroll
        for (int b = 0; b < 4; b++)
#pragma unroll
            for (int c = 0; c < 4; c++) acc[a][b][c] = 0.0f;

    int arow0 = wm*64 + (lane & 15);
    int achk  = lane >> 4;             // 0/1
    int brow0 = wn*32 + (lane & 7);
    int bchk  = (lane >> 3) & 1;       // 0/1

    for (int kt = 0; kt < NK; kt++){
        // explicit tail-aware waits; exactly one group per real stage pending
        if (kt + 2 < NK)      asm volatile("cp.async.wait_group 2;" ::: "memory");
        else if (kt + 1 < NK) asm volatile("cp.async.wait_group 1;" ::: "memory");
        else                  asm volatile("cp.async.wait_group 0;" ::: "memory");
        __syncthreads();

        uint32_t st = sm + (kt % 3)*STAGE_BYTES;
#pragma unroll
        for (int ks = 0; ks < 4; ks++){
            uint32_t ahf[4][4], alf[4][4], bhf[4][2], blf[4][2];
#pragma unroll
            for (int mt = 0; mt < 4; mt++){
                int r = arow0 + mt*16;
                int c = ks*2 + achk;
                uint32_t soff = (uint32_t)r*128u + (uint32_t)(((c ^ (r & 7)) & 7)*16);
                ldm_x4(ahf[mt], st + OFF_AH + soff);
                ldm_x4(alf[mt], st + OFF_AL + soff);
            }
#pragma unroll
            for (int nt = 0; nt < 4; nt++){
                int r = brow0 + nt*8;
                int c = ks*2 + bchk;
                uint32_t soff = (uint32_t)r*128u + (uint32_t)(((c ^ (r & 7)) & 7)*16);
                ldm_x2(bhf[nt], st + OFF_BH + soff);
                ldm_x2(blf[nt], st + OFF_BL + soff);
            }
#pragma unroll
            for (int mt = 0; mt < 4; mt++)
#pragma unroll
                for (int nt = 0; nt < 4; nt++){
                    mma16816(acc[mt][nt], ahf[mt], bhf[nt]);
                    mma16816(acc[mt][nt], ahf[mt], blf[nt]);
                    mma16816(acc[mt][nt], alf[mt], bhf[nt]);
                }
        }
        __syncthreads();
        if (kt + 3 < NK){
            copy_stage(kt + 3, kt % 3);
            asm volatile("cp.async.commit_group;" ::: "memory");
        }
    }

    // epilogue
    int g   = lane >> 2;
    int tgi = lane & 3;
#pragma unroll
    for (int mt = 0; mt < 4; mt++){
#pragma unroll
        for (int h = 0; h < 2; h++){
            int r = wm*64 + mt*16 + g + h*8;
            int m = m0 + r;
            if (EXPERT && m >= cnt) continue;
            float w = 1.0f;
            size_t rowbase;
            if (EXPERT){
                int p = base + m;
                w = g_pair_w[p];
                rowbase = (size_t)p * DOWND;
            } else {
                rowbase = (size_t)m * HID;
            }
#pragma unroll
            for (int nt = 0; nt < 4; nt++){
                int col = n0 + wn*32 + nt*8 + tgi*2;
                float2 v;
                v.x = (acc[mt][nt][2*h+0] + __ldg(bptr + col    )) * w;
                v.y = (acc[mt][nt][2*h+1] + __ldg(bptr + col + 1)) * w;
                *(float2*)&C[rowbase + col] = v;
            }
        }
    }
}

// ---------------- combine + gelu -> bf16 hi/lo ----------------
__global__ void k_combine(){
    int idx = blockIdx.x * blockDim.x + threadIdx.x;   // over NTOK*DOWND/4
    int n = idx >> 7;
    int d = idx & 127;
    int p0 = g_tok_pair[2*n], p1 = g_tok_pair[2*n+1];
    float4 v0 = *(const float4*)&g_eo[(size_t)p0*DOWND + 4*d];
    float4 v1 = *(const float4*)&g_eo[(size_t)p1*DOWND + 4*d];
    float g0 = gelu_new(v0.x + v1.x);
    float g1 = gelu_new(v0.y + v1.y);
    float g2 = gelu_new(v0.z + v1.z);
    float g3 = gelu_new(v0.w + v1.w);
    __nv_bfloat16 h0 = __float2bfloat16(g0), h1 = __float2bfloat16(g1);
    __nv_bfloat16 h2 = __float2bfloat16(g2), h3 = __float2bfloat16(g3);
    __nv_bfloat16 l0 = __float2bfloat16(g0 - __bfloat162float(h0));
    __nv_bfloat16 l1 = __float2bfloat16(g1 - __bfloat162float(h1));
    __nv_bfloat16 l2 = __float2bfloat16(g2 - __bfloat162float(h2));
    __nv_bfloat16 l3 = __float2bfloat16(g3 - __bfloat162float(h3));
    size_t o = (size_t)n*DOWND + 4*d;
    ((__nv_bfloat162*)&g_hh[o])[0] = __nv_bfloat162(h0, h1);
    ((__nv_bfloat162*)&g_hh[o])[1] = __nv_bfloat162(h2, h3);
    ((__nv_bfloat162*)&g_hl[o])[0] = __nv_bfloat162(l0, l1);
    ((__nv_bfloat162*)&g_hl[o])[1] = __nv_bfloat162(l2, l3);
}

// ---------------- launch ----------------
extern "C" void kernel_launch(void* const* d_in, const int* in_sizes, int n_in,
                              void* d_out, int out_size){
    const float* x      = (const float*)d_in[0];
    const float* gate_w = (const float*)d_in[1];
    const float* down_w = (const float*)d_in[2];
    const float* down_b = (const float*)d_in[3];
    const float* up_w   = (const float*)d_in[4];
    const float* up_b   = (const float*)d_in[5];
    float* out = (float*)d_out;

    // REAL device addresses of __device__ symbols (host shadow names are NOT
    // device pointers — that was the R5 bug).
    void *p_xh, *p_xl, *p_wh, *p_wl, *p_uh, *p_ul, *p_hh, *p_hl, *p_eo;
    cudaGetSymbolAddress(&p_xh, g_xh);
    cudaGetSymbolAddress(&p_xl, g_xl);
    cudaGetSymbolAddress(&p_wh, g_wh);
    cudaGetSymbolAddress(&p_wl, g_wl);
    cudaGetSymbolAddress(&p_uh, g_uh);
    cudaGetSymbolAddress(&p_ul, g_ul);
    cudaGetSymbolAddress(&p_hh, g_hh);
    cudaGetSymbolAddress(&p_hl, g_hl);
    cudaGetSymbolAddress(&p_eo, g_eo);

    cudaFuncSetAttribute(k_gemm<true,  HID>,   cudaFuncAttributeMaxDynamicSharedMemorySize, GSMEM);
    cudaFuncSetAttribute(k_gemm<false, DOWND>, cudaFuncAttributeMaxDynamicSharedMemorySize, GSMEM);

    k_init<<<1, 32>>>();
    k_gate<<<NTOK/8, 256>>>(x, gate_w);
    k_prefix<<<1, 1>>>(out + (size_t)NTOK * HID);   // loss scalar after [B,S,HIDDEN]
    k_scatter<<<NTOK/256, 256>>>();

    // bf16 hi/lo conversions
    k_cvt<<<(NTOK*HID/4 + 255)/256, 256>>>(x, (__nv_bfloat16*)p_xh, (__nv_bfloat16*)p_xl, NTOK*HID/4);
    k_cvt<<<(NE*DOWND*HID/4 + 255)/256, 256>>>(down_w, (__nv_bfloat16*)p_wh, (__nv_bfloat16*)p_wl, NE*DOWND*HID/4);
    k_cvt<<<(HID*DOWND/4 + 255)/256, 256>>>(up_w, (__nv_bfloat16*)p_uh, (__nv_bfloat16*)p_ul, HID*DOWND/4);

    // grouped expert GEMM: C[pair, down] = (Xg . We^T + b_e) * w_pair
    dim3 ge(64, DOWND/128, NE);    // 64 m-tiles covers worst-case skew
    k_gemm<true, HID><<<ge, 256, GSMEM>>>(
        (const __nv_bfloat16*)p_xh, (const __nv_bfloat16*)p_xl,
        (const __nv_bfloat16*)p_wh, (const __nv_bfloat16*)p_wl,
        down_b, (float*)p_eo);

    k_combine<<<(NTOK*DOWND/4)/256, 256>>>();

    // up projection: out = h . up_w^T + up_b
    dim3 gu(NTOK/128, HID/128);
    k_gemm<false, DOWND><<<gu, 256, GSMEM>>>(
        (const __nv_bfloat16*)p_hh, (const __nv_bfloat16*)p_hl,
        (const __nv_bfloat16*)p_uh, (const __nv_bfloat16*)p_ul,
        up_b, out);
}

// round 7
// speedup vs baseline: 2.5901x; 1.0173x over previous
#include <cuda_runtime.h>
#include <cuda_bf16.h>
#include <math.h>
#include <stdint.h>

#define HID   2048
#define DOWND 512
#define NE    16
#define NTOK  8192
#define NPAIR (NTOK*2)

// ---------------- scratch (static device memory; no allocs allowed) ----------------
__device__ float g_eo[NPAIR*DOWND];          // scaled expert outputs (fp32)
__device__ __nv_bfloat16 g_xh[NTOK*HID];     // x split hi/lo
__device__ __nv_bfloat16 g_xl[NTOK*HID];
__device__ __nv_bfloat16 g_wh[NE*DOWND*HID]; // down_w split hi/lo
__device__ __nv_bfloat16 g_wl[NE*DOWND*HID];
__device__ __nv_bfloat16 g_uh[HID*DOWND];    // up_w split hi/lo
__device__ __nv_bfloat16 g_ul[HID*DOWND];
__device__ __nv_bfloat16 g_hh[NTOK*DOWND];   // gelu(combined) split hi/lo
__device__ __nv_bfloat16 g_hl[NTOK*DOWND];
__device__ int   g_pair_tok[NPAIR];
__device__ float g_pair_w [NPAIR];
__device__ int   g_tok_pair[NTOK*2];
__device__ int   g_ei[NTOK*2];
__device__ float g_wp[NTOK*2];
__device__ int   g_cnt[NE];
__device__ int   g_off[NE];
__device__ int   g_cur[NE];
__device__ float g_sum[NE];

// ---------------- PTX helpers (Ampere-class: valid on compute_103 base) ----------------
__device__ __forceinline__ uint32_t smem_u32(const void* p){
    uint32_t a;
    asm("{ .reg .u64 t; cvta.to.shared.u64 t, %1; cvt.u32.u64 %0, t; }" : "=r"(a) : "l"(p));
    return a;
}
__device__ __forceinline__ void cpa16(uint32_t saddr, const void* g){
    asm volatile("cp.async.cg.shared.global [%0], [%1], 16;" :: "r"(saddr), "l"(g));
}
__device__ __forceinline__ void ldm_x4(uint32_t* r, uint32_t addr){
    asm volatile("ldmatrix.sync.aligned.m8n8.x4.shared.b16 {%0,%1,%2,%3}, [%4];"
        : "=r"(r[0]), "=r"(r[1]), "=r"(r[2]), "=r"(r[3]) : "r"(addr));
}
__device__ __forceinline__ void mma16816(float* c, const uint32_t* a, const uint32_t* b){
    asm volatile("mma.sync.aligned.m16n8k16.row.col.f32.bf16.bf16.f32 "
        "{%0,%1,%2,%3}, {%4,%5,%6,%7}, {%8,%9}, {%0,%1,%2,%3};"
        : "+f"(c[0]), "+f"(c[1]), "+f"(c[2]), "+f"(c[3])
        : "r"(a[0]), "r"(a[1]), "r"(a[2]), "r"(a[3]), "r"(b[0]), "r"(b[1]));
}

__device__ __forceinline__ float gelu_new(float v){
    float c = v + 0.044715f * v * v * v;
    return 0.5f * v * (1.0f + tanhf(0.7978845608028654f * c));
}

// ---------------- routing kernels ----------------
__global__ void k_init(){
    int t = threadIdx.x;
    if (t < NE){ g_cnt[t] = 0; g_sum[t] = 0.0f; }
}

// warp per token: gate logits + top-2 softmax; ALSO writes x hi/lo bf16 split
__global__ void k_gate(const float* __restrict__ x, const float* __restrict__ gw,
                       __nv_bfloat16* __restrict__ xh, __nv_bfloat16* __restrict__ xl){
    int w    = threadIdx.x >> 5;
    int lane = threadIdx.x & 31;
    int n = blockIdx.x * 8 + w;
    const float4* xr = (const float4*)(x + (size_t)n * HID);
    const float4* g4 = (const float4*)gw;
    float acc[NE];
#pragma unroll
    for (int e = 0; e < NE; e++) acc[e] = 0.0f;
    for (int i = 0; i < 16; i++){
        int j = lane + 32*i;
        float4 xv = xr[j];
        // fused hi/lo split write
        __nv_bfloat16 h0 = __float2bfloat16(xv.x);
        __nv_bfloat16 h1 = __float2bfloat16(xv.y);
        __nv_bfloat16 h2 = __float2bfloat16(xv.z);
        __nv_bfloat16 h3 = __float2bfloat16(xv.w);
        __nv_bfloat16 l0 = __float2bfloat16(xv.x - __bfloat162float(h0));
        __nv_bfloat16 l1 = __float2bfloat16(xv.y - __bfloat162float(h1));
        __nv_bfloat16 l2 = __float2bfloat16(xv.z - __bfloat162float(h2));
        __nv_bfloat16 l3 = __float2bfloat16(xv.w - __bfloat162float(h3));
        size_t o = (size_t)n*HID + (size_t)j*4;
        ((__nv_bfloat162*)(xh + o))[0] = __nv_bfloat162(h0, h1);
        ((__nv_bfloat162*)(xh + o))[1] = __nv_bfloat162(h2, h3);
        ((__nv_bfloat162*)(xl + o))[0] = __nv_bfloat162(l0, l1);
        ((__nv_bfloat162*)(xl + o))[1] = __nv_bfloat162(l2, l3);
#pragma unroll
        for (int e = 0; e < NE; e++){
            float4 gv = g4[e*(HID/4) + j];
            acc[e] += xv.x*gv.x + xv.y*gv.y + xv.z*gv.z + xv.w*gv.w;
        }
    }
#pragma unroll
    for (int e = 0; e < NE; e++){
#pragma unroll
        for (int o = 16; o > 0; o >>= 1)
            acc[e] += __shfl_xor_sync(0xffffffffu, acc[e], o);
    }
    if (lane == 0){
        float v0 = -1e30f, v1 = -1e30f; int i0 = 0, i1 = 0;
#pragma unroll
        for (int e = 0; e < NE; e++){
            float v = acc[e];
            if (v > v0){ v1 = v0; i1 = i0; v0 = v; i0 = e; }
            else if (v > v1){ v1 = v; i1 = e; }
        }
        float ee = expf(v1 - v0);
        float s  = 1.0f + ee;
        float w0 = 1.0f / s, w1 = ee / s;
        g_ei[2*n]   = i0; g_ei[2*n+1] = i1;
        g_wp[2*n]   = w0; g_wp[2*n+1] = w1;
        atomicAdd(&g_cnt[i0], 1);  atomicAdd(&g_cnt[i1], 1);
        atomicAdd(&g_sum[i0], w0); atomicAdd(&g_sum[i1], w1);
    }
}

__global__ void k_prefix(float* __restrict__ loss_out){
    if (threadIdx.x == 0 && blockIdx.x == 0){
        int a = 0; float ls = 0.0f;
        for (int e = 0; e < NE; e++){
            g_off[e] = a; g_cur[e] = a; a += g_cnt[e];
            float t = g_sum[e] / (float)NTOK;
            ls += t * t;
        }
        *loss_out = (float)NE * ls * 0.1f;
    }
}

__global__ void k_scatter(){
    int n = blockIdx.x * blockDim.x + threadIdx.x;
    if (n >= NTOK) return;
#pragma unroll
    for (int s = 0; s < 2; s++){
        int e = g_ei[2*n+s];
        int p = atomicAdd(&g_cur[e], 1);
        g_pair_tok[p] = n;
        g_pair_w [p]  = g_wp[2*n+s];
        g_tok_pair[2*n+s] = p;
    }
}

// ---------------- fp32 -> bf16 hi/lo split conversion (weights) ----------------
__global__ void k_cvt(const float* __restrict__ in, __nv_bfloat16* __restrict__ h,
                      __nv_bfloat16* __restrict__ l, int n4){
    int i = blockIdx.x * blockDim.x + threadIdx.x;
    if (i >= n4) return;
    float4 v = ((const float4*)in)[i];
    __nv_bfloat16 h0 = __float2bfloat16(v.x);
    __nv_bfloat16 h1 = __float2bfloat16(v.y);
    __nv_bfloat16 h2 = __float2bfloat16(v.z);
    __nv_bfloat16 h3 = __float2bfloat16(v.w);
    __nv_bfloat16 l0 = __float2bfloat16(v.x - __bfloat162float(h0));
    __nv_bfloat16 l1 = __float2bfloat16(v.y - __bfloat162float(h1));
    __nv_bfloat16 l2 = __float2bfloat16(v.z - __bfloat162float(h2));
    __nv_bfloat16 l3 = __float2bfloat16(v.w - __bfloat162float(h3));
    __nv_bfloat162* hp = (__nv_bfloat162*)h;
    __nv_bfloat162* lp = (__nv_bfloat162*)l;
    hp[2*i]   = __nv_bfloat162(h0, h1);
    hp[2*i+1] = __nv_bfloat162(h2, h3);
    lp[2*i]   = __nv_bfloat162(l0, l1);
    lp[2*i+1] = __nv_bfloat162(l2, l3);
}

// ---------------- warp-MMA GEMM (bf16 3-term split, fp32 accum) ----------------
// Block 256x128, BK=64, 8 warps (4x2), warp tile 64x64. 2-stage cp.async pipeline.
// Stage: Ah/Al 256x128B + Bh/Bl 128x128B = 96KB. 2 stages = 192KB dyn smem.
#define STAGE_BYTES 98304
#define OFF_AH 0
#define OFF_AL 32768
#define OFF_BH 65536
#define OFF_BL 81920
#define GSMEM  (2*STAGE_BYTES)

template<bool EXPERT, int KDIM>
__global__ void __launch_bounds__(256, 1)
k_gemm(const __nv_bfloat16* __restrict__ Ah, const __nv_bfloat16* __restrict__ Al,
       const __nv_bfloat16* __restrict__ Bh, const __nv_bfloat16* __restrict__ Bl,
       const float* __restrict__ bias, float* __restrict__ C)
{
    int e   = EXPERT ? blockIdx.z : 0;
    int cnt = EXPERT ? g_cnt[e] : NTOK;
    int m0  = blockIdx.x * 256;
    if (m0 >= cnt) return;
    int base = EXPERT ? g_off[e] : 0;
    int n0   = blockIdx.y * 128;
    const float* bptr = EXPERT ? bias + e*DOWND : bias;

    extern __shared__ char smem[];
    uint32_t sm = smem_u32(smem);
    __shared__ int s_aoff[256];
    __shared__ int s_boff[128];

    int tid  = threadIdx.x;
    int lane = tid & 31;
    int wid  = tid >> 5;
    int wm   = wid >> 1;      // 0..3 (M)
    int wn   = wid & 1;       // 0..1 (N)

    {
        int m = m0 + tid;
        int ar;
        if (EXPERT) ar = g_pair_tok[base + ((m < cnt) ? m : 0)];
        else        ar = m;
        s_aoff[tid] = ar * KDIM;
        if (tid < 128){
            int bn = (EXPERT ? e*DOWND : 0) + n0 + tid;
            s_boff[tid] = bn * KDIM;
        }
    }
    __syncthreads();

    const int NK = KDIM / 64;

    auto copy_stage = [&](int kt, int buf){
        uint32_t st = sm + buf*STAGE_BYTES;
        int kbase = kt*64;
#pragma unroll
        for (int i = 0; i < 8; i++){
            int idx = tid + i*256;          // 0..2047 -> A rows 0..255
            int row = idx >> 3;
            int c   = idx & 7;
            uint32_t soff = (uint32_t)row*128u + (uint32_t)((c ^ (row & 7))*16);
            int ga = s_aoff[row] + kbase + c*8;
            cpa16(st + OFF_AH + soff, Ah + ga);
            cpa16(st + OFF_AL + soff, Al + ga);
        }
#pragma unroll
        for (int i = 0; i < 4; i++){
            int idx = tid + i*256;          // 0..1023 -> B rows 0..127
            int row = idx >> 3;
            int c   = idx & 7;
            uint32_t soff = (uint32_t)row*128u + (uint32_t)((c ^ (row & 7))*16);
            int gb = s_boff[row] + kbase + c*8;
            cpa16(st + OFF_BH + soff, Bh + gb);
            cpa16(st + OFF_BL + soff, Bl + gb);
        }
    };

    copy_stage(0, 0);
    asm volatile("cp.async.commit_group;" ::: "memory");
    if (NK > 1){ copy_stage(1, 1); asm volatile("cp.async.commit_group;" ::: "memory"); }

    float acc[4][8][4];
#pragma unroll
    for (int a = 0; a < 4; a++)
#pragma unroll
        for (int b = 0; b < 8; b++)
#pragma unroll
            for (int c = 0; c < 4; c++) acc[a][b][c] = 0.0f;

    int arow0 = wm*64 + (lane & 15);
    int achk  = lane >> 4;                       // 0/1
    int bgrp  = lane >> 3;                       // 0..3
    int brow0 = wn*64 + (bgrp >> 1)*8 + (lane & 7);
    int bchk  = bgrp & 1;                        // 0/1

    for (int kt = 0; kt < NK; kt++){
        if (kt + 1 < NK) asm volatile("cp.async.wait_group 1;" ::: "memory");
        else             asm volatile("cp.async.wait_group 0;" ::: "memory");
        __syncthreads();

        uint32_t st = sm + (kt & 1)*STAGE_BYTES;
#pragma unroll
        for (int ks = 0; ks < 4; ks++){
            uint32_t ahf[4][4], alf[4][4];
#pragma unroll
            for (int mt = 0; mt < 4; mt++){
                int r = arow0 + mt*16;
                int c = ks*2 + achk;
                uint32_t soff = (uint32_t)r*128u + (uint32_t)(((c ^ (r & 7)) & 7)*16);
                ldm_x4(ahf[mt], st + OFF_AH + soff);
                ldm_x4(alf[mt], st + OFF_AL + soff);
            }
#pragma unroll
            for (int ntp = 0; ntp < 4; ntp++){
                int r = brow0 + ntp*16;
                int c = ks*2 + bchk;
                uint32_t soff = (uint32_t)r*128u + (uint32_t)(((c ^ (r & 7)) & 7)*16);
                uint32_t bh4[4], bl4[4];
                ldm_x4(bh4, st + OFF_BH + soff);
                ldm_x4(bl4, st + OFF_BL + soff);
#pragma unroll
                for (int mt = 0; mt < 4; mt++){
                    mma16816(acc[mt][2*ntp  ], ahf[mt], bh4    );
                    mma16816(acc[mt][2*ntp  ], ahf[mt], bl4    );
                    mma16816(acc[mt][2*ntp  ], alf[mt], bh4    );
                    mma16816(acc[mt][2*ntp+1], ahf[mt], bh4 + 2);
                    mma16816(acc[mt][2*ntp+1], ahf[mt], bl4 + 2);
                    mma16816(acc[mt][2*ntp+1], alf[mt], bh4 + 2);
                }
            }
        }
        __syncthreads();
        if (kt + 2 < NK){
            copy_stage(kt + 2, kt & 1);
            asm volatile("cp.async.commit_group;" ::: "memory");
        }
    }

    // epilogue
    int g   = lane >> 2;
    int tgi = lane & 3;
#pragma unroll
    for (int mt = 0; mt < 4; mt++){
#pragma unroll
        for (int h = 0; h < 2; h++){
            int r = wm*64 + mt*16 + g + h*8;
            int m = m0 + r;
            if (EXPERT && m >= cnt) continue;
            float w = 1.0f;
            size_t rowbase;
            if (EXPERT){
                int p = base + m;
                w = g_pair_w[p];
                rowbase = (size_t)p * DOWND;
            } else {
                rowbase = (size_t)m * HID;
            }
#pragma unroll
            for (int nt = 0; nt < 8; nt++){
                int col = n0 + wn*64 + nt*8 + tgi*2;
                float2 v;
                v.x = (acc[mt][nt][2*h+0] + __ldg(bptr + col    )) * w;
                v.y = (acc[mt][nt][2*h+1] + __ldg(bptr + col + 1)) * w;
                *(float2*)&C[rowbase + col] = v;
            }
        }
    }
}

// ---------------- combine + gelu -> bf16 hi/lo ----------------
__global__ void k_combine(){
    int idx = blockIdx.x * blockDim.x + threadIdx.x;   // over NTOK*DOWND/4
    int n = idx >> 7;
    int d = idx & 127;
    int p0 = g_tok_pair[2*n], p1 = g_tok_pair[2*n+1];
    float4 v0 = *(const float4*)&g_eo[(size_t)p0*DOWND + 4*d];
    float4 v1 = *(const float4*)&g_eo[(size_t)p1*DOWND + 4*d];
    float g0 = gelu_new(v0.x + v1.x);
    float g1 = gelu_new(v0.y + v1.y);
    float g2 = gelu_new(v0.z + v1.z);
    float g3 = gelu_new(v0.w + v1.w);
    __nv_bfloat16 h0 = __float2bfloat16(g0), h1 = __float2bfloat16(g1);
    __nv_bfloat16 h2 = __float2bfloat16(g2), h3 = __float2bfloat16(g3);
    __nv_bfloat16 l0 = __float2bfloat16(g0 - __bfloat162float(h0));
    __nv_bfloat16 l1 = __float2bfloat16(g1 - __bfloat162float(h1));
    __nv_bfloat16 l2 = __float2bfloat16(g2 - __bfloat162float(h2));
    __nv_bfloat16 l3 = __float2bfloat16(g3 - __bfloat162float(h3));
    size_t o = (size_t)n*DOWND + 4*d;
    ((__nv_bfloat162*)&g_hh[o])[0] = __nv_bfloat162(h0, h1);
    ((__nv_bfloat162*)&g_hh[o])[1] = __nv_bfloat162(h2, h3);
    ((__nv_bfloat162*)&g_hl[o])[0] = __nv_bfloat162(l0, l1);
    ((__nv_bfloat162*)&g_hl[o])[1] = __nv_bfloat162(l2, l3);
}

// ---------------- launch ----------------
extern "C" void kernel_launch(void* const* d_in, const int* in_sizes, int n_in,
                              void* d_out, int out_size){
    const float* x      = (const float*)d_in[0];
    const float* gate_w = (const float*)d_in[1];
    const float* down_w = (const float*)d_in[2];
    const float* down_b = (const float*)d_in[3];
    const float* up_w   = (const float*)d_in[4];
    const float* up_b   = (const float*)d_in[5];
    float* out = (float*)d_out;

    // REAL device addresses of __device__ symbols (host shadows are not device ptrs)
    void *p_xh, *p_xl, *p_wh, *p_wl, *p_uh, *p_ul, *p_hh, *p_hl, *p_eo;
    cudaGetSymbolAddress(&p_xh, g_xh);
    cudaGetSymbolAddress(&p_xl, g_xl);
    cudaGetSymbolAddress(&p_wh, g_wh);
    cudaGetSymbolAddress(&p_wl, g_wl);
    cudaGetSymbolAddress(&p_uh, g_uh);
    cudaGetSymbolAddress(&p_ul, g_ul);
    cudaGetSymbolAddress(&p_hh, g_hh);
    cudaGetSymbolAddress(&p_hl, g_hl);
    cudaGetSymbolAddress(&p_eo, g_eo);

    cudaFuncSetAttribute(k_gemm<true,  HID>,   cudaFuncAttributeMaxDynamicSharedMemorySize, GSMEM);
    cudaFuncSetAttribute(k_gemm<false, DOWND>, cudaFuncAttributeMaxDynamicSharedMemorySize, GSMEM);

    k_init<<<1, 32>>>();
    k_gate<<<NTOK/8, 256>>>(x, gate_w, (__nv_bfloat16*)p_xh, (__nv_bfloat16*)p_xl);
    k_prefix<<<1, 1>>>(out + (size_t)NTOK * HID);   // loss scalar after [B,S,HIDDEN]
    k_scatter<<<NTOK/256, 256>>>();

    // weight hi/lo conversions
    k_cvt<<<(NE*DOWND*HID/4 + 255)/256, 256>>>(down_w, (__nv_bfloat16*)p_wh, (__nv_bfloat16*)p_wl, NE*DOWND*HID/4);
    k_cvt<<<(HID*DOWND/4 + 255)/256, 256>>>(up_w, (__nv_bfloat16*)p_uh, (__nv_bfloat16*)p_ul, HID*DOWND/4);

    // grouped expert GEMM: C[pair, down] = (Xg . We^T + b_e) * w_pair
    dim3 ge(32, DOWND/128, NE);   // 32 m-tiles of 256 covers worst-case skew
    k_gemm<true, HID><<<ge, 256, GSMEM>>>(
        (const __nv_bfloat16*)p_xh, (const __nv_bfloat16*)p_xl,
        (const __nv_bfloat16*)p_wh, (const __nv_bfloat16*)p_wl,
        down_b, (float*)p_eo);

    k_combine<<<(NTOK*DOWND/4)/256, 256>>>();

    // up projection: out = h . up_w^T + up_b
    dim3 gu(NTOK/256, HID/128);
    k_gemm<false, DOWND><<<gu, 256, GSMEM>>>(
        (const __nv_bfloat16*)p_hh, (const __nv_bfloat16*)p_hl,
        (const __nv_bfloat16*)p_uh, (const __nv_bfloat16*)p_ul,
        up_b, out);
}

// round 8
// speedup vs baseline: 2.6338x; 1.0169x over previous
#include <cuda_runtime.h>
#include <cuda_bf16.h>
#include <math.h>
#include <stdint.h>

#define HID   2048
#define DOWND 512
#define NE    16
#define NTOK  8192
#define NPAIR (NTOK*2)

// ---------------- scratch (static device memory; no allocs allowed) ----------------
__device__ float g_eo[NPAIR*DOWND];          // scaled expert outputs (fp32)
__device__ __nv_bfloat16 g_xh[NTOK*HID];     // x split hi/lo
__device__ __nv_bfloat16 g_xl[NTOK*HID];
__device__ __nv_bfloat16 g_wh[NE*DOWND*HID]; // down_w split hi/lo
__device__ __nv_bfloat16 g_wl[NE*DOWND*HID];
__device__ __nv_bfloat16 g_uh[HID*DOWND];    // up_w split hi/lo
__device__ __nv_bfloat16 g_ul[HID*DOWND];
__device__ __nv_bfloat16 g_hh[NTOK*DOWND];   // gelu(combined) split hi/lo
__device__ __nv_bfloat16 g_hl[NTOK*DOWND];
__device__ int   g_pair_tok[NPAIR];
__device__ float g_pair_w [NPAIR];
__device__ int   g_tok_pair[NTOK*2];
__device__ int   g_ei[NTOK*2];
__device__ float g_wp[NTOK*2];
__device__ int   g_cnt[NE];
__device__ int   g_off[NE];
__device__ int   g_cur[NE];
__device__ float g_sum[NE];

// ---------------- PTX helpers (Ampere-class: valid on compute_103 base) ----------------
__device__ __forceinline__ uint32_t smem_u32(const void* p){
    uint32_t a;
    asm("{ .reg .u64 t; cvta.to.shared.u64 t, %1; cvt.u32.u64 %0, t; }" : "=r"(a) : "l"(p));
    return a;
}
__device__ __forceinline__ void cpa16(uint32_t saddr, const void* g){
    asm volatile("cp.async.cg.shared.global [%0], [%1], 16;" :: "r"(saddr), "l"(g));
}
__device__ __forceinline__ void ldm_x4(uint32_t* r, uint32_t addr){
    asm volatile("ldmatrix.sync.aligned.m8n8.x4.shared.b16 {%0,%1,%2,%3}, [%4];"
        : "=r"(r[0]), "=r"(r[1]), "=r"(r[2]), "=r"(r[3]) : "r"(addr));
}
__device__ __forceinline__ void mma16816(float* c, const uint32_t* a, const uint32_t* b){
    asm volatile("mma.sync.aligned.m16n8k16.row.col.f32.bf16.bf16.f32 "
        "{%0,%1,%2,%3}, {%4,%5,%6,%7}, {%8,%9}, {%0,%1,%2,%3};"
        : "+f"(c[0]), "+f"(c[1]), "+f"(c[2]), "+f"(c[3])
        : "r"(a[0]), "r"(a[1]), "r"(a[2]), "r"(a[3]), "r"(b[0]), "r"(b[1]));
}

__device__ __forceinline__ float gelu_new(float v){
    float c = v + 0.044715f * v * v * v;
    return 0.5f * v * (1.0f + tanhf(0.7978845608028654f * c));
}

// ---------------- routing kernels ----------------
__global__ void k_init(){
    int t = threadIdx.x;
    if (t < NE){ g_cnt[t] = 0; g_sum[t] = 0.0f; }
}

// warp per token: gate logits + top-2 softmax; ALSO writes x hi/lo bf16 split
__global__ void k_gate(const float* __restrict__ x, const float* __restrict__ gw,
                       __nv_bfloat16* __restrict__ xh, __nv_bfloat16* __restrict__ xl){
    int w    = threadIdx.x >> 5;
    int lane = threadIdx.x & 31;
    int n = blockIdx.x * 8 + w;
    const float4* xr = (const float4*)(x + (size_t)n * HID);
    const float4* g4 = (const float4*)gw;
    float acc[NE];
#pragma unroll
    for (int e = 0; e < NE; e++) acc[e] = 0.0f;
    for (int i = 0; i < 16; i++){
        int j = lane + 32*i;
        float4 xv = xr[j];
        __nv_bfloat16 h0 = __float2bfloat16(xv.x);
        __nv_bfloat16 h1 = __float2bfloat16(xv.y);
        __nv_bfloat16 h2 = __float2bfloat16(xv.z);
        __nv_bfloat16 h3 = __float2bfloat16(xv.w);
        __nv_bfloat16 l0 = __float2bfloat16(xv.x - __bfloat162float(h0));
        __nv_bfloat16 l1 = __float2bfloat16(xv.y - __bfloat162float(h1));
        __nv_bfloat16 l2 = __float2bfloat16(xv.z - __bfloat162float(h2));
        __nv_bfloat16 l3 = __float2bfloat16(xv.w - __bfloat162float(h3));
        size_t o = (size_t)n*HID + (size_t)j*4;
        ((__nv_bfloat162*)(xh + o))[0] = __nv_bfloat162(h0, h1);
        ((__nv_bfloat162*)(xh + o))[1] = __nv_bfloat162(h2, h3);
        ((__nv_bfloat162*)(xl + o))[0] = __nv_bfloat162(l0, l1);
        ((__nv_bfloat162*)(xl + o))[1] = __nv_bfloat162(l2, l3);
#pragma unroll
        for (int e = 0; e < NE; e++){
            float4 gv = g4[e*(HID/4) + j];
            acc[e] += xv.x*gv.x + xv.y*gv.y + xv.z*gv.z + xv.w*gv.w;
        }
    }
#pragma unroll
    for (int e = 0; e < NE; e++){
#pragma unroll
        for (int o = 16; o > 0; o >>= 1)
            acc[e] += __shfl_xor_sync(0xffffffffu, acc[e], o);
    }
    if (lane == 0){
        float v0 = -1e30f, v1 = -1e30f; int i0 = 0, i1 = 0;
#pragma unroll
        for (int e = 0; e < NE; e++){
            float v = acc[e];
            if (v > v0){ v1 = v0; i1 = i0; v0 = v; i0 = e; }
            else if (v > v1){ v1 = v; i1 = e; }
        }
        float ee = expf(v1 - v0);
        float s  = 1.0f + ee;
        float w0 = 1.0f / s, w1 = ee / s;
        g_ei[2*n]   = i0; g_ei[2*n+1] = i1;
        g_wp[2*n]   = w0; g_wp[2*n+1] = w1;
        atomicAdd(&g_cnt[i0], 1);  atomicAdd(&g_cnt[i1], 1);
        atomicAdd(&g_sum[i0], w0); atomicAdd(&g_sum[i1], w1);
    }
}

__global__ void k_prefix(float* __restrict__ loss_out){
    if (threadIdx.x == 0 && blockIdx.x == 0){
        int a = 0; float ls = 0.0f;
        for (int e = 0; e < NE; e++){
            g_off[e] = a; g_cur[e] = a; a += g_cnt[e];
            float t = g_sum[e] / (float)NTOK;
            ls += t * t;
        }
        *loss_out = (float)NE * ls * 0.1f;
    }
}

__global__ void k_scatter(){
    int n = blockIdx.x * blockDim.x + threadIdx.x;
    if (n >= NTOK) return;
#pragma unroll
    for (int s = 0; s < 2; s++){
        int e = g_ei[2*n+s];
        int p = atomicAdd(&g_cur[e], 1);
        g_pair_tok[p] = n;
        g_pair_w [p]  = g_wp[2*n+s];
        g_tok_pair[2*n+s] = p;
    }
}

// ---------------- fp32 -> bf16 hi/lo split conversion (weights) ----------------
__global__ void k_cvt(const float* __restrict__ in, __nv_bfloat16* __restrict__ h,
                      __nv_bfloat16* __restrict__ l, int n4){
    int i = blockIdx.x * blockDim.x + threadIdx.x;
    if (i >= n4) return;
    float4 v = ((const float4*)in)[i];
    __nv_bfloat16 h0 = __float2bfloat16(v.x);
    __nv_bfloat16 h1 = __float2bfloat16(v.y);
    __nv_bfloat16 h2 = __float2bfloat16(v.z);
    __nv_bfloat16 h3 = __float2bfloat16(v.w);
    __nv_bfloat16 l0 = __float2bfloat16(v.x - __bfloat162float(h0));
    __nv_bfloat16 l1 = __float2bfloat16(v.y - __bfloat162float(h1));
    __nv_bfloat16 l2 = __float2bfloat16(v.z - __bfloat162float(h2));
    __nv_bfloat16 l3 = __float2bfloat16(v.w - __bfloat162float(h3));
    __nv_bfloat162* hp = (__nv_bfloat162*)h;
    __nv_bfloat162* lp = (__nv_bfloat162*)l;
    hp[2*i]   = __nv_bfloat162(h0, h1);
    hp[2*i+1] = __nv_bfloat162(h2, h3);
    lp[2*i]   = __nv_bfloat162(l0, l1);
    lp[2*i+1] = __nv_bfloat162(l2, l3);
}

// ---------------- warp-MMA GEMM (bf16 3-term split, fp32 accum) ----------------
// Block 128x128, BK=32, 4 warps (2x2), warp tile 64x64. 3-stage cp.async pipeline.
// Each SMEM row = 128B packing [hi 64B | lo 64B] for one logical row's 32-K slice.
// Stage = A 16KB + B 16KB = 32KB; 3 stages = 96KB -> 2 CTAs/SM.
#define STAGE_BYTES 32768
#define OFF_A 0
#define OFF_B 16384
#define GSMEM  (3*STAGE_BYTES)

template<bool EXPERT, int KDIM>
__global__ void __launch_bounds__(128, 2)
k_gemm(const __nv_bfloat16* __restrict__ Ah, const __nv_bfloat16* __restrict__ Al,
       const __nv_bfloat16* __restrict__ Bh, const __nv_bfloat16* __restrict__ Bl,
       const float* __restrict__ bias, float* __restrict__ C)
{
    int e   = EXPERT ? blockIdx.z : 0;
    int cnt = EXPERT ? g_cnt[e] : NTOK;
    int m0  = blockIdx.x * 128;
    if (m0 >= cnt) return;
    int base = EXPERT ? g_off[e] : 0;
    int n0   = blockIdx.y * 128;
    const float* bptr = EXPERT ? bias + e*DOWND : bias;

    extern __shared__ char smem[];
    uint32_t sm = smem_u32(smem);
    __shared__ int s_aoff[128];
    __shared__ int s_boff[128];

    int tid  = threadIdx.x;
    int lane = tid & 31;
    int wid  = tid >> 5;
    int wm   = wid >> 1;      // 0..1 (M)
    int wn   = wid & 1;       // 0..1 (N)

    {
        int m = m0 + tid;
        int ar;
        if (EXPERT) ar = g_pair_tok[base + ((m < cnt) ? m : 0)];
        else        ar = m;
        s_aoff[tid] = ar * KDIM;
        int bn = (EXPERT ? e*DOWND : 0) + n0 + tid;
        s_boff[tid] = bn * KDIM;
    }
    __syncthreads();

    const int NK = KDIM / 32;

    // stage layout: row r (128B) = [hi k0..31 | lo k0..31], SW128 XOR swizzle
    auto copy_stage = [&](int kt, int buf){
        uint32_t st = sm + buf*STAGE_BYTES;
        int kbase = kt*32;
        int c   = tid & 7;            // constant per thread
        int rb  = tid >> 3;           // row base 0..15
        bool hi = (c < 4);
        int ksub = (c & 3) * 8;
#pragma unroll
        for (int i = 0; i < 8; i++){
            int row = rb + i*16;
            uint32_t soff = (uint32_t)row*128u + (uint32_t)((c ^ (row & 7))*16);
            const __nv_bfloat16* src = (hi ? Ah : Al) + s_aoff[row] + kbase + ksub;
            cpa16(st + OFF_A + soff, src);
        }
#pragma unroll
        for (int i = 0; i < 8; i++){
            int row = rb + i*16;
            uint32_t soff = (uint32_t)row*128u + (uint32_t)((c ^ (row & 7))*16);
            const __nv_bfloat16* src = (hi ? Bh : Bl) + s_boff[row] + kbase + ksub;
            cpa16(st + OFF_B + soff, src);
        }
    };

    copy_stage(0, 0);
    asm volatile("cp.async.commit_group;" ::: "memory");
    copy_stage(1, 1);
    asm volatile("cp.async.commit_group;" ::: "memory");
    copy_stage(2, 2);
    asm volatile("cp.async.commit_group;" ::: "memory");

    float acc[4][8][4];
#pragma unroll
    for (int a = 0; a < 4; a++)
#pragma unroll
        for (int b = 0; b < 8; b++)
#pragma unroll
            for (int c = 0; c < 4; c++) acc[a][b][c] = 0.0f;

    int arow0 = wm*64 + (lane & 15);
    int achk  = lane >> 4;                       // 0/1
    int bgrp  = lane >> 3;                       // 0..3
    int brow0 = wn*64 + (bgrp >> 1)*8 + (lane & 7);
    int bchk  = bgrp & 1;                        // 0/1

    for (int kt = 0; kt < NK; kt++){
        if (kt + 2 < NK)      asm volatile("cp.async.wait_group 2;" ::: "memory");
        else if (kt + 1 < NK) asm volatile("cp.async.wait_group 1;" ::: "memory");
        else                  asm volatile("cp.async.wait_group 0;" ::: "memory");
        __syncthreads();

        uint32_t st = sm + (kt % 3)*STAGE_BYTES;
#pragma unroll
        for (int ks = 0; ks < 2; ks++){
            uint32_t ahf[4][4], alf[4][4];
#pragma unroll
            for (int mt = 0; mt < 4; mt++){
                int r  = arow0 + mt*16;
                int ch = ks*2 + achk;           // hi chunk 0..3
                uint32_t sh = (uint32_t)r*128u + (uint32_t)(((ch    ) ^ (r & 7))*16);
                uint32_t sl = (uint32_t)r*128u + (uint32_t)(((ch + 4) ^ (r & 7))*16);
                ldm_x4(ahf[mt], st + OFF_A + sh);
                ldm_x4(alf[mt], st + OFF_A + sl);
            }
#pragma unroll
            for (int ntp = 0; ntp < 4; ntp++){
                int r  = brow0 + ntp*16;
                int ch = ks*2 + bchk;
                uint32_t sh = (uint32_t)r*128u + (uint32_t)(((ch    ) ^ (r & 7))*16);
                uint32_t sl = (uint32_t)r*128u + (uint32_t)(((ch + 4) ^ (r & 7))*16);
                uint32_t bh4[4], bl4[4];
                ldm_x4(bh4, st + OFF_B + sh);
                ldm_x4(bl4, st + OFF_B + sl);
                // term-major: 3 passes of 8 independent MMAs (chain distance 8)
#pragma unroll
                for (int mt = 0; mt < 4; mt++){
                    mma16816(acc[mt][2*ntp  ], ahf[mt], bh4    );
                    mma16816(acc[mt][2*ntp+1], ahf[mt], bh4 + 2);
                }
#pragma unroll
                for (int mt = 0; mt < 4; mt++){
                    mma16816(acc[mt][2*ntp  ], ahf[mt], bl4    );
                    mma16816(acc[mt][2*ntp+1], ahf[mt], bl4 + 2);
                }
#pragma unroll
                for (int mt = 0; mt < 4; mt++){
                    mma16816(acc[mt][2*ntp  ], alf[mt], bh4    );
                    mma16816(acc[mt][2*ntp+1], alf[mt], bh4 + 2);
                }
            }
        }
        __syncthreads();
        if (kt + 3 < NK){
            copy_stage(kt + 3, kt % 3);
            asm volatile("cp.async.commit_group;" ::: "memory");
        }
    }

    // epilogue
    int g   = lane >> 2;
    int tgi = lane & 3;
#pragma unroll
    for (int mt = 0; mt < 4; mt++){
#pragma unroll
        for (int h = 0; h < 2; h++){
            int r = wm*64 + mt*16 + g + h*8;
            int m = m0 + r;
            if (EXPERT && m >= cnt) continue;
            float w = 1.0f;
            size_t rowbase;
            if (EXPERT){
                int p = base + m;
                w = g_pair_w[p];
                rowbase = (size_t)p * DOWND;
            } else {
                rowbase = (size_t)m * HID;
            }
#pragma unroll
            for (int nt = 0; nt < 8; nt++){
                int col = n0 + wn*64 + nt*8 + tgi*2;
                float2 v;
                v.x = (acc[mt][nt][2*h+0] + __ldg(bptr + col    )) * w;
                v.y = (acc[mt][nt][2*h+1] + __ldg(bptr + col + 1)) * w;
                *(float2*)&C[rowbase + col] = v;
            }
        }
    }
}

// ---------------- combine + gelu -> bf16 hi/lo ----------------
__global__ void k_combine(){
    int idx = blockIdx.x * blockDim.x + threadIdx.x;   // over NTOK*DOWND/4
    int n = idx >> 7;
    int d = idx & 127;
    int p0 = g_tok_pair[2*n], p1 = g_tok_pair[2*n+1];
    float4 v0 = *(const float4*)&g_eo[(size_t)p0*DOWND + 4*d];
    float4 v1 = *(const float4*)&g_eo[(size_t)p1*DOWND + 4*d];
    float g0 = gelu_new(v0.x + v1.x);
    float g1 = gelu_new(v0.y + v1.y);
    float g2 = gelu_new(v0.z + v1.z);
    float g3 = gelu_new(v0.w + v1.w);
    __nv_bfloat16 h0 = __float2bfloat16(g0), h1 = __float2bfloat16(g1);
    __nv_bfloat16 h2 = __float2bfloat16(g2), h3 = __float2bfloat16(g3);
    __nv_bfloat16 l0 = __float2bfloat16(g0 - __bfloat162float(h0));
    __nv_bfloat16 l1 = __float2bfloat16(g1 - __bfloat162float(h1));
    __nv_bfloat16 l2 = __float2bfloat16(g2 - __bfloat162float(h2));
    __nv_bfloat16 l3 = __float2bfloat16(g3 - __bfloat162float(h3));
    size_t o = (size_t)n*DOWND + 4*d;
    ((__nv_bfloat162*)&g_hh[o])[0] = __nv_bfloat162(h0, h1);
    ((__nv_bfloat162*)&g_hh[o])[1] = __nv_bfloat162(h2, h3);
    ((__nv_bfloat162*)&g_hl[o])[0] = __nv_bfloat162(l0, l1);
    ((__nv_bfloat162*)&g_hl[o])[1] = __nv_bfloat162(l2, l3);
}

// ---------------- launch ----------------
extern "C" void kernel_launch(void* const* d_in, const int* in_sizes, int n_in,
                              void* d_out, int out_size){
    const float* x      = (const float*)d_in[0];
    const float* gate_w = (const float*)d_in[1];
    const float* down_w = (const float*)d_in[2];
    const float* down_b = (const float*)d_in[3];
    const float* up_w   = (const float*)d_in[4];
    const float* up_b   = (const float*)d_in[5];
    float* out = (float*)d_out;

    // REAL device addresses of __device__ symbols (host shadows are not device ptrs)
    void *p_xh, *p_xl, *p_wh, *p_wl, *p_uh, *p_ul, *p_hh, *p_hl, *p_eo;
    cudaGetSymbolAddress(&p_xh, g_xh);
    cudaGetSymbolAddress(&p_xl, g_xl);
    cudaGetSymbolAddress(&p_wh, g_wh);
    cudaGetSymbolAddress(&p_wl, g_wl);
    cudaGetSymbolAddress(&p_uh, g_uh);
    cudaGetSymbolAddress(&p_ul, g_ul);
    cudaGetSymbolAddress(&p_hh, g_hh);
    cudaGetSymbolAddress(&p_hl, g_hl);
    cudaGetSymbolAddress(&p_eo, g_eo);

    cudaFuncSetAttribute(k_gemm<true,  HID>,   cudaFuncAttributeMaxDynamicSharedMemorySize, GSMEM);
    cudaFuncSetAttribute(k_gemm<false, DOWND>, cudaFuncAttributeMaxDynamicSharedMemorySize, GSMEM);

    k_init<<<1, 32>>>();
    k_gate<<<NTOK/8, 256>>>(x, gate_w, (__nv_bfloat16*)p_xh, (__nv_bfloat16*)p_xl);
    k_prefix<<<1, 1>>>(out + (size_t)NTOK * HID);   // loss scalar after [B,S,HIDDEN]
    k_scatter<<<NTOK/256, 256>>>();

    // weight hi/lo conversions
    k_cvt<<<(NE*DOWND*HID/4 + 255)/256, 256>>>(down_w, (__nv_bfloat16*)p_wh, (__nv_bfloat16*)p_wl, NE*DOWND*HID/4);
    k_cvt<<<(HID*DOWND/4 + 255)/256, 256>>>(up_w, (__nv_bfloat16*)p_uh, (__nv_bfloat16*)p_ul, HID*DOWND/4);

    // grouped expert GEMM: C[pair, down] = (Xg . We^T + b_e) * w_pair
    dim3 ge(64, DOWND/128, NE);   // 64 m-tiles of 128 covers worst-case skew
    k_gemm<true, HID><<<ge, 128, GSMEM>>>(
        (const __nv_bfloat16*)p_xh, (const __nv_bfloat16*)p_xl,
        (const __nv_bfloat16*)p_wh, (const __nv_bfloat16*)p_wl,
        down_b, (float*)p_eo);

    k_combine<<<(NTOK*DOWND/4)/256, 256>>>();

    // up projection: out = h . up_w^T + up_b
    dim3 gu(NTOK/128, HID/128);
    k_gemm<false, DOWND><<<gu, 128, GSMEM>>>(
        (const __nv_bfloat16*)p_hh, (const __nv_bfloat16*)p_hl,
        (const __nv_bfloat16*)p_uh, (const __nv_bfloat16*)p_ul,
        up_b, out);
}

// round 9
// speedup vs baseline: 3.7929x; 1.4401x over previous
#include <cuda_runtime.h>
#include <cuda_fp16.h>
#include <math.h>
#include <stdint.h>

#define HID   2048
#define DOWND 512
#define NE    16
#define NTOK  8192
#define NPAIR (NTOK*2)

// ---------------- scratch (static device memory; no allocs allowed) ----------------
__device__ float  g_eo[NPAIR*DOWND];       // scaled expert outputs (fp32)
__device__ __half g_xh[NTOK*HID];          // x as fp16 (A side, single)
__device__ __half g_wh[NE*DOWND*HID];      // down_w fp16 hi
__device__ __half g_wl[NE*DOWND*HID];      // down_w fp16 lo
__device__ __half g_uh[HID*DOWND];         // up_w fp16 hi
__device__ __half g_ul[HID*DOWND];         // up_w fp16 lo
__device__ __half g_hh[NTOK*DOWND];        // gelu(combined) fp16 (A side, single)
__device__ int   g_pair_tok[NPAIR];
__device__ float g_pair_w [NPAIR];
__device__ int   g_tok_pair[NTOK*2];
__device__ int   g_ei[NTOK*2];
__device__ float g_wp[NTOK*2];
__device__ int   g_cnt[NE];
__device__ int   g_off[NE];
__device__ int   g_cur[NE];
__device__ float g_sum[NE];

// ---------------- PTX helpers (Ampere-class: valid on compute_103 base) ----------------
__device__ __forceinline__ uint32_t smem_u32(const void* p){
    uint32_t a;
    asm("{ .reg .u64 t; cvta.to.shared.u64 t, %1; cvt.u32.u64 %0, t; }" : "=r"(a) : "l"(p));
    return a;
}
__device__ __forceinline__ void cpa16(uint32_t saddr, const void* g){
    asm volatile("cp.async.cg.shared.global [%0], [%1], 16;" :: "r"(saddr), "l"(g));
}
__device__ __forceinline__ void ldm_x4(uint32_t* r, uint32_t addr){
    asm volatile("ldmatrix.sync.aligned.m8n8.x4.shared.b16 {%0,%1,%2,%3}, [%4];"
        : "=r"(r[0]), "=r"(r[1]), "=r"(r[2]), "=r"(r[3]) : "r"(addr));
}
__device__ __forceinline__ void mma16816(float* c, const uint32_t* a, const uint32_t* b){
    asm volatile("mma.sync.aligned.m16n8k16.row.col.f32.f16.f16.f32 "
        "{%0,%1,%2,%3}, {%4,%5,%6,%7}, {%8,%9}, {%0,%1,%2,%3};"
        : "+f"(c[0]), "+f"(c[1]), "+f"(c[2]), "+f"(c[3])
        : "r"(a[0]), "r"(a[1]), "r"(a[2]), "r"(a[3]), "r"(b[0]), "r"(b[1]));
}

__device__ __forceinline__ float gelu_new(float v){
    float c = v + 0.044715f * v * v * v;
    return 0.5f * v * (1.0f + tanhf(0.7978845608028654f * c));
}

// ---------------- routing kernels ----------------
__global__ void k_init(){
    int t = threadIdx.x;
    if (t < NE){ g_cnt[t] = 0; g_sum[t] = 0.0f; }
}

// warp per token: gate logits + top-2 softmax; ALSO writes x as fp16
__global__ void k_gate(const float* __restrict__ x, const float* __restrict__ gw,
                       __half* __restrict__ xh){
    int w    = threadIdx.x >> 5;
    int lane = threadIdx.x & 31;
    int n = blockIdx.x * 8 + w;
    const float4* xr = (const float4*)(x + (size_t)n * HID);
    const float4* g4 = (const float4*)gw;
    float acc[NE];
#pragma unroll
    for (int e = 0; e < NE; e++) acc[e] = 0.0f;
    for (int i = 0; i < 16; i++){
        int j = lane + 32*i;
        float4 xv = xr[j];
        __half2 h01 = __floats2half2_rn(xv.x, xv.y);
        __half2 h23 = __floats2half2_rn(xv.z, xv.w);
        size_t o = (size_t)n*HID + (size_t)j*4;
        ((__half2*)(xh + o))[0] = h01;
        ((__half2*)(xh + o))[1] = h23;
#pragma unroll
        for (int e = 0; e < NE; e++){
            float4 gv = g4[e*(HID/4) + j];
            acc[e] += xv.x*gv.x + xv.y*gv.y + xv.z*gv.z + xv.w*gv.w;
        }
    }
#pragma unroll
    for (int e = 0; e < NE; e++){
#pragma unroll
        for (int o = 16; o > 0; o >>= 1)
            acc[e] += __shfl_xor_sync(0xffffffffu, acc[e], o);
    }
    if (lane == 0){
        float v0 = -1e30f, v1 = -1e30f; int i0 = 0, i1 = 0;
#pragma unroll
        for (int e = 0; e < NE; e++){
            float v = acc[e];
            if (v > v0){ v1 = v0; i1 = i0; v0 = v; i0 = e; }
            else if (v > v1){ v1 = v; i1 = e; }
        }
        float ee = expf(v1 - v0);
        float s  = 1.0f + ee;
        float w0 = 1.0f / s, w1 = ee / s;
        g_ei[2*n]   = i0; g_ei[2*n+1] = i1;
        g_wp[2*n]   = w0; g_wp[2*n+1] = w1;
        atomicAdd(&g_cnt[i0], 1);  atomicAdd(&g_cnt[i1], 1);
        atomicAdd(&g_sum[i0], w0); atomicAdd(&g_sum[i1], w1);
    }
}

__global__ void k_prefix(float* __restrict__ loss_out){
    if (threadIdx.x == 0 && blockIdx.x == 0){
        int a = 0; float ls = 0.0f;
        for (int e = 0; e < NE; e++){
            g_off[e] = a; g_cur[e] = a; a += g_cnt[e];
            float t = g_sum[e] / (float)NTOK;
            ls += t * t;
        }
        *loss_out = (float)NE * ls * 0.1f;
    }
}

__global__ void k_scatter(){
    int n = blockIdx.x * blockDim.x + threadIdx.x;
    if (n >= NTOK) return;
#pragma unroll
    for (int s = 0; s < 2; s++){
        int e = g_ei[2*n+s];
        int p = atomicAdd(&g_cur[e], 1);
        g_pair_tok[p] = n;
        g_pair_w [p]  = g_wp[2*n+s];
        g_tok_pair[2*n+s] = p;
    }
}

// ---------------- fp32 -> fp16 hi/lo split (weights) ----------------
__global__ void k_cvt(const float* __restrict__ in, __half* __restrict__ h,
                      __half* __restrict__ l, int n4){
    int i = blockIdx.x * blockDim.x + threadIdx.x;
    if (i >= n4) return;
    float4 v = ((const float4*)in)[i];
    __half h0 = __float2half_rn(v.x);
    __half h1 = __float2half_rn(v.y);
    __half h2 = __float2half_rn(v.z);
    __half h3 = __float2half_rn(v.w);
    __half l0 = __float2half_rn(v.x - __half2float(h0));
    __half l1 = __float2half_rn(v.y - __half2float(h1));
    __half l2 = __float2half_rn(v.z - __half2float(h2));
    __half l3 = __float2half_rn(v.w - __half2float(h3));
    ((__half2*)h)[2*i]   = __halves2half2(h0, h1);
    ((__half2*)h)[2*i+1] = __halves2half2(h2, h3);
    ((__half2*)l)[2*i]   = __halves2half2(l0, l1);
    ((__half2*)l)[2*i+1] = __halves2half2(l2, l3);
}

// ---------------- warp-MMA GEMM (fp16 2-term split, fp32 accum) ----------------
// Block 128x128, BK=32, 4 warps (2x2), warp tile 64x64. 4-stage cp.async pipeline.
// A: single fp16, rows 64B (stride 64), col swizzle (c ^ ((row>>1)&3)).
// B: [hi 64B | lo 64B] per 128B row, col swizzle (c ^ (row&7)).
// Stage = A 8KB + B 16KB = 24KB; 4 stages = 96KB -> 2 CTAs/SM.
#define STAGE_BYTES 24576
#define OFF_A 0
#define OFF_B 8192
#define GSMEM  (4*STAGE_BYTES)

template<bool EXPERT, int KDIM>
__global__ void __launch_bounds__(128, 2)
k_gemm(const __half* __restrict__ A,
       const __half* __restrict__ Bh, const __half* __restrict__ Bl,
       const float* __restrict__ bias, float* __restrict__ C)
{
    int e   = EXPERT ? blockIdx.z : 0;
    int cnt = EXPERT ? g_cnt[e] : NTOK;
    int m0  = blockIdx.x * 128;
    if (m0 >= cnt) return;
    int base = EXPERT ? g_off[e] : 0;
    int n0   = blockIdx.y * 128;
    const float* bptr = EXPERT ? bias + e*DOWND : bias;

    extern __shared__ char smem[];
    uint32_t sm = smem_u32(smem);
    __shared__ int s_aoff[128];
    __shared__ int s_boff[128];

    int tid  = threadIdx.x;
    int lane = tid & 31;
    int wid  = tid >> 5;
    int wm   = wid >> 1;      // 0..1 (M)
    int wn   = wid & 1;       // 0..1 (N)

    {
        int m = m0 + tid;
        int ar;
        if (EXPERT) ar = g_pair_tok[base + ((m < cnt) ? m : 0)];
        else        ar = m;
        s_aoff[tid] = ar * KDIM;
        int bn = (EXPERT ? e*DOWND : 0) + n0 + tid;
        s_boff[tid] = bn * KDIM;
    }
    __syncthreads();

    const int NK = KDIM / 32;

    auto copy_stage = [&](int kt, int buf){
        uint32_t st = sm + buf*STAGE_BYTES;
        int kbase = kt*32;
        // A: 128 rows x 4 chunks of 16B (8 fp16)
#pragma unroll
        for (int i = 0; i < 4; i++){
            int idx = tid + i*128;            // 0..511
            int row = idx >> 2;
            int c   = idx & 3;
            uint32_t soff = (uint32_t)row*64u + (uint32_t)((c ^ ((row>>1)&3))<<4);
            cpa16(st + OFF_A + soff, A + s_aoff[row] + kbase + c*8);
        }
        // B: 128 rows x 8 chunks (hi c<4, lo c>=4)
#pragma unroll
        for (int i = 0; i < 8; i++){
            int idx = tid + i*128;            // 0..1023
            int row = idx >> 3;
            int c   = idx & 7;
            bool hi = (c < 4);
            int ksub = (c & 3) * 8;
            uint32_t soff = (uint32_t)row*128u + (uint32_t)((c ^ (row & 7))<<4);
            const __half* src = (hi ? Bh : Bl) + s_boff[row] + kbase + ksub;
            cpa16(st + OFF_B + soff, src);
        }
    };

    copy_stage(0, 0);
    asm volatile("cp.async.commit_group;" ::: "memory");
    copy_stage(1, 1);
    asm volatile("cp.async.commit_group;" ::: "memory");
    copy_stage(2, 2);
    asm volatile("cp.async.commit_group;" ::: "memory");

    float acc[4][8][4];
#pragma unroll
    for (int a = 0; a < 4; a++)
#pragma unroll
        for (int b = 0; b < 8; b++)
#pragma unroll
            for (int c = 0; c < 4; c++) acc[a][b][c] = 0.0f;

    int arow0 = wm*64 + (lane & 15);
    int achk  = lane >> 4;                       // 0/1
    int bgrp  = lane >> 3;                       // 0..3
    int brow0 = wn*64 + (bgrp >> 1)*8 + (lane & 7);
    int bchk  = bgrp & 1;                        // 0/1

    for (int kt = 0; kt < NK; kt++){
        if (kt + 2 < NK)      asm volatile("cp.async.wait_group 2;" ::: "memory");
        else if (kt + 1 < NK) asm volatile("cp.async.wait_group 1;" ::: "memory");
        else                  asm volatile("cp.async.wait_group 0;" ::: "memory");
        __syncthreads();

        uint32_t st = sm + (kt & 3)*STAGE_BYTES;
#pragma unroll
        for (int ks = 0; ks < 2; ks++){
            uint32_t ahf[4][4];
#pragma unroll
            for (int mt = 0; mt < 4; mt++){
                int r  = arow0 + mt*16;
                int ch = ks*2 + achk;            // 0..3
                uint32_t sa = (uint32_t)r*64u + (uint32_t)((ch ^ ((r>>1)&3))<<4);
                ldm_x4(ahf[mt], st + OFF_A + sa);
            }
#pragma unroll
            for (int ntp = 0; ntp < 4; ntp++){
                int r  = brow0 + ntp*16;
                int ch = ks*2 + bchk;            // 0..3 (hi), +4 (lo)
                uint32_t sh = (uint32_t)r*128u + (uint32_t)(((ch    ) ^ (r & 7))<<4);
                uint32_t sl = (uint32_t)r*128u + (uint32_t)(((ch + 4) ^ (r & 7))<<4);
                uint32_t bh4[4], bl4[4];
                ldm_x4(bh4, st + OFF_B + sh);
                ldm_x4(bl4, st + OFF_B + sl);
                // 2 term-passes of 8 independent MMAs (accumulator chain dist 8)
#pragma unroll
                for (int mt = 0; mt < 4; mt++){
                    mma16816(acc[mt][2*ntp  ], ahf[mt], bh4    );
                    mma16816(acc[mt][2*ntp+1], ahf[mt], bh4 + 2);
                }
#pragma unroll
                for (int mt = 0; mt < 4; mt++){
                    mma16816(acc[mt][2*ntp  ], ahf[mt], bl4    );
                    mma16816(acc[mt][2*ntp+1], ahf[mt], bl4 + 2);
                }
            }
        }
        __syncthreads();
        if (kt + 3 < NK){
            copy_stage(kt + 3, (kt + 3) & 3);
            asm volatile("cp.async.commit_group;" ::: "memory");
        }
    }

    // epilogue
    int g   = lane >> 2;
    int tgi = lane & 3;
#pragma unroll
    for (int mt = 0; mt < 4; mt++){
#pragma unroll
        for (int h = 0; h < 2; h++){
            int r = wm*64 + mt*16 + g + h*8;
            int m = m0 + r;
            if (EXPERT && m >= cnt) continue;
            float w = 1.0f;
            size_t rowbase;
            if (EXPERT){
                int p = base + m;
                w = g_pair_w[p];
                rowbase = (size_t)p * DOWND;
            } else {
                rowbase = (size_t)m * HID;
            }
#pragma unroll
            for (int nt = 0; nt < 8; nt++){
                int col = n0 + wn*64 + nt*8 + tgi*2;
                float2 v;
                v.x = (acc[mt][nt][2*h+0] + __ldg(bptr + col    )) * w;
                v.y = (acc[mt][nt][2*h+1] + __ldg(bptr + col + 1)) * w;
                *(float2*)&C[rowbase + col] = v;
            }
        }
    }
}

// ---------------- combine + gelu -> fp16 ----------------
__global__ void k_combine(){
    int idx = blockIdx.x * blockDim.x + threadIdx.x;   // over NTOK*DOWND/4
    int n = idx >> 7;
    int d = idx & 127;
    int p0 = g_tok_pair[2*n], p1 = g_tok_pair[2*n+1];
    float4 v0 = *(const float4*)&g_eo[(size_t)p0*DOWND + 4*d];
    float4 v1 = *(const float4*)&g_eo[(size_t)p1*DOWND + 4*d];
    float g0 = gelu_new(v0.x + v1.x);
    float g1 = gelu_new(v0.y + v1.y);
    float g2 = gelu_new(v0.z + v1.z);
    float g3 = gelu_new(v0.w + v1.w);
    size_t o = (size_t)n*DOWND + 4*d;
    ((__half2*)&g_hh[o])[0] = __floats2half2_rn(g0, g1);
    ((__half2*)&g_hh[o])[1] = __floats2half2_rn(g2, g3);
}

// ---------------- launch ----------------
extern "C" void kernel_launch(void* const* d_in, const int* in_sizes, int n_in,
                              void* d_out, int out_size){
    const float* x      = (const float*)d_in[0];
    const float* gate_w = (const float*)d_in[1];
    const float* down_w = (const float*)d_in[2];
    const float* down_b = (const float*)d_in[3];
    const float* up_w   = (const float*)d_in[4];
    const float* up_b   = (const float*)d_in[5];
    float* out = (float*)d_out;

    // REAL device addresses of __device__ symbols
    void *p_xh, *p_wh, *p_wl, *p_uh, *p_ul, *p_hh, *p_eo;
    cudaGetSymbolAddress(&p_xh, g_xh);
    cudaGetSymbolAddress(&p_wh, g_wh);
    cudaGetSymbolAddress(&p_wl, g_wl);
    cudaGetSymbolAddress(&p_uh, g_uh);
    cudaGetSymbolAddress(&p_ul, g_ul);
    cudaGetSymbolAddress(&p_hh, g_hh);
    cudaGetSymbolAddress(&p_eo, g_eo);

    cudaFuncSetAttribute(k_gemm<true,  HID>,   cudaFuncAttributeMaxDynamicSharedMemorySize, GSMEM);
    cudaFuncSetAttribute(k_gemm<false, DOWND>, cudaFuncAttributeMaxDynamicSharedMemorySize, GSMEM);

    k_init<<<1, 32>>>();
    k_gate<<<NTOK/8, 256>>>(x, gate_w, (__half*)p_xh);
    k_prefix<<<1, 1>>>(out + (size_t)NTOK * HID);   // loss scalar after [B,S,HIDDEN]
    k_scatter<<<NTOK/256, 256>>>();

    // weight fp16 hi/lo conversions
    k_cvt<<<(NE*DOWND*HID/4 + 255)/256, 256>>>(down_w, (__half*)p_wh, (__half*)p_wl, NE*DOWND*HID/4);
    k_cvt<<<(HID*DOWND/4 + 255)/256, 256>>>(up_w, (__half*)p_uh, (__half*)p_ul, HID*DOWND/4);

    // grouped expert GEMM: C[pair, down] = (Xg . We^T + b_e) * w_pair
    dim3 ge(64, DOWND/128, NE);   // 64 m-tiles of 128 covers worst-case skew
    k_gemm<true, HID><<<ge, 128, GSMEM>>>(
        (const __half*)p_xh,
        (const __half*)p_wh, (const __half*)p_wl,
        down_b, (float*)p_eo);

    k_combine<<<(NTOK*DOWND/4)/256, 256>>>();

    // up projection: out = h . up_w^T + up_b
    dim3 gu(NTOK/128, HID/128);
    k_gemm<false, DOWND><<<gu, 128, GSMEM>>>(
        (const __half*)p_hh,
        (const __half*)p_uh, (const __half*)p_ul,
        up_b, out);
}

// round 10
// speedup vs baseline: 4.8116x; 1.2686x over previous
#include <cuda_runtime.h>
#include <cuda_fp16.h>
#include <math.h>
#include <stdint.h>

#define HID   2048
#define DOWND 512
#define NE    16
#define NTOK  8192
#define NPAIR (NTOK*2)

// ---------------- scratch (static device memory; no allocs allowed) ----------------
__device__ float  g_eo[NPAIR*DOWND];       // scaled expert outputs (fp32)
__device__ __half g_xh[NTOK*HID];          // x as fp16
__device__ __half g_wh[NE*DOWND*HID];      // down_w fp16
__device__ __half g_uh[HID*DOWND];         // up_w fp16
__device__ __half g_hh[NTOK*DOWND];        // gelu(combined) fp16
__device__ int   g_pair_tok[NPAIR];
__device__ float g_pair_w [NPAIR];
__device__ int   g_tok_pair[NTOK*2];
__device__ int   g_ei[NTOK*2];
__device__ float g_wp[NTOK*2];
__device__ int   g_cnt[NE];
__device__ int   g_off[NE];
__device__ int   g_cur[NE];
__device__ float g_sum[NE];

// ---------------- PTX helpers (Ampere-class: valid on compute_103 base) ----------------
__device__ __forceinline__ uint32_t smem_u32(const void* p){
    uint32_t a;
    asm("{ .reg .u64 t; cvta.to.shared.u64 t, %1; cvt.u32.u64 %0, t; }" : "=r"(a) : "l"(p));
    return a;
}
__device__ __forceinline__ void cpa16(uint32_t saddr, const void* g){
    asm volatile("cp.async.cg.shared.global [%0], [%1], 16;" :: "r"(saddr), "l"(g));
}
__device__ __forceinline__ void ldm_x4(uint32_t* r, uint32_t addr){
    asm volatile("ldmatrix.sync.aligned.m8n8.x4.shared.b16 {%0,%1,%2,%3}, [%4];"
        : "=r"(r[0]), "=r"(r[1]), "=r"(r[2]), "=r"(r[3]) : "r"(addr));
}
__device__ __forceinline__ void mma16816(float* c, const uint32_t* a, const uint32_t* b){
    asm volatile("mma.sync.aligned.m16n8k16.row.col.f32.f16.f16.f32 "
        "{%0,%1,%2,%3}, {%4,%5,%6,%7}, {%8,%9}, {%0,%1,%2,%3};"
        : "+f"(c[0]), "+f"(c[1]), "+f"(c[2]), "+f"(c[3])
        : "r"(a[0]), "r"(a[1]), "r"(a[2]), "r"(a[3]), "r"(b[0]), "r"(b[1]));
}

__device__ __forceinline__ float gelu_new(float v){
    float c = v + 0.044715f * v * v * v;
    return 0.5f * v * (1.0f + tanhf(0.7978845608028654f * c));
}

// ---------------- routing kernels ----------------
__global__ void k_init(){
    int t = threadIdx.x;
    if (t < NE){ g_cnt[t] = 0; g_sum[t] = 0.0f; }
}

// warp per token: gate logits + top-2 softmax; ALSO writes x as fp16
__global__ void k_gate(const float* __restrict__ x, const float* __restrict__ gw,
                       __half* __restrict__ xh){
    int w    = threadIdx.x >> 5;
    int lane = threadIdx.x & 31;
    int n = blockIdx.x * 8 + w;
    const float4* xr = (const float4*)(x + (size_t)n * HID);
    const float4* g4 = (const float4*)gw;
    float acc[NE];
#pragma unroll
    for (int e = 0; e < NE; e++) acc[e] = 0.0f;
    for (int i = 0; i < 16; i++){
        int j = lane + 32*i;
        float4 xv = xr[j];
        size_t o = (size_t)n*HID + (size_t)j*4;
        ((__half2*)(xh + o))[0] = __floats2half2_rn(xv.x, xv.y);
        ((__half2*)(xh + o))[1] = __floats2half2_rn(xv.z, xv.w);
#pragma unroll
        for (int e = 0; e < NE; e++){
            float4 gv = g4[e*(HID/4) + j];
            acc[e] += xv.x*gv.x + xv.y*gv.y + xv.z*gv.z + xv.w*gv.w;
        }
    }
#pragma unroll
    for (int e = 0; e < NE; e++){
#pragma unroll
        for (int o = 16; o > 0; o >>= 1)
            acc[e] += __shfl_xor_sync(0xffffffffu, acc[e], o);
    }
    if (lane == 0){
        float v0 = -1e30f, v1 = -1e30f; int i0 = 0, i1 = 0;
#pragma unroll
        for (int e = 0; e < NE; e++){
            float v = acc[e];
            if (v > v0){ v1 = v0; i1 = i0; v0 = v; i0 = e; }
            else if (v > v1){ v1 = v; i1 = e; }
        }
        float ee = expf(v1 - v0);
        float s  = 1.0f + ee;
        float w0 = 1.0f / s, w1 = ee / s;
        g_ei[2*n]   = i0; g_ei[2*n+1] = i1;
        g_wp[2*n]   = w0; g_wp[2*n+1] = w1;
        atomicAdd(&g_cnt[i0], 1);  atomicAdd(&g_cnt[i1], 1);
        atomicAdd(&g_sum[i0], w0); atomicAdd(&g_sum[i1], w1);
    }
}

__global__ void k_prefix(float* __restrict__ loss_out){
    if (threadIdx.x == 0 && blockIdx.x == 0){
        int a = 0; float ls = 0.0f;
        for (int e = 0; e < NE; e++){
            g_off[e] = a; g_cur[e] = a; a += g_cnt[e];
            float t = g_sum[e] / (float)NTOK;
            ls += t * t;
        }
        *loss_out = (float)NE * ls * 0.1f;
    }
}

__global__ void k_scatter(){
    int n = blockIdx.x * blockDim.x + threadIdx.x;
    if (n >= NTOK) return;
#pragma unroll
    for (int s = 0; s < 2; s++){
        int e = g_ei[2*n+s];
        int p = atomicAdd(&g_cur[e], 1);
        g_pair_tok[p] = n;
        g_pair_w [p]  = g_wp[2*n+s];
        g_tok_pair[2*n+s] = p;
    }
}

// ---------------- fp32 -> fp16 conversion (weights) ----------------
__global__ void k_cvt1(const float* __restrict__ in, __half* __restrict__ h, int n4){
    int i = blockIdx.x * blockDim.x + threadIdx.x;
    if (i >= n4) return;
    float4 v = ((const float4*)in)[i];
    ((__half2*)h)[2*i]   = __floats2half2_rn(v.x, v.y);
    ((__half2*)h)[2*i+1] = __floats2half2_rn(v.z, v.w);
}

// ---------------- warp-MMA GEMM (single fp16, fp32 accum) ----------------
// Block 128x128, BK=32, 4 warps (2x2), warp tile 64x64. 6-stage cp.async pipeline.
// A and B: fp16 rows of 64B (4 x 16B chunks), col swizzle (c ^ ((row>>1)&3)).
// Stage = A 8KB + B 8KB = 16KB; 6 stages = 96KB -> 2 CTAs/SM.
#define STAGE_BYTES 16384
#define OFF_A 0
#define OFF_B 8192
#define GSMEM  (6*STAGE_BYTES)

template<bool EXPERT, int KDIM>
__global__ void __launch_bounds__(128, 2)
k_gemm(const __half* __restrict__ A, const __half* __restrict__ B,
       const float* __restrict__ bias, float* __restrict__ C)
{
    int e   = EXPERT ? blockIdx.z : 0;
    int cnt = EXPERT ? g_cnt[e] : NTOK;
    int m0  = blockIdx.x * 128;
    if (m0 >= cnt) return;
    int base = EXPERT ? g_off[e] : 0;
    int n0   = blockIdx.y * 128;
    const float* bptr = EXPERT ? bias + e*DOWND : bias;

    extern __shared__ char smem[];
    uint32_t sm = smem_u32(smem);
    __shared__ int s_aoff[128];
    __shared__ int s_boff[128];

    int tid  = threadIdx.x;
    int lane = tid & 31;
    int wid  = tid >> 5;
    int wm   = wid >> 1;      // 0..1 (M)
    int wn   = wid & 1;       // 0..1 (N)

    {
        int m = m0 + tid;
        int ar;
        if (EXPERT) ar = g_pair_tok[base + ((m < cnt) ? m : 0)];
        else        ar = m;
        s_aoff[tid] = ar * KDIM;
        int bn = (EXPERT ? e*DOWND : 0) + n0 + tid;
        s_boff[tid] = bn * KDIM;
    }
    __syncthreads();

    const int NK = KDIM / 32;   // >= 16 always

    auto copy_stage = [&](int kt, int buf){
        uint32_t st = sm + buf*STAGE_BYTES;
        int kbase = kt*32;
#pragma unroll
        for (int i = 0; i < 4; i++){
            int idx = tid + i*128;            // 0..511
            int row = idx >> 2;
            int c   = idx & 3;
            uint32_t soff = (uint32_t)row*64u + (uint32_t)((c ^ ((row>>1)&3))<<4);
            cpa16(st + OFF_A + soff, A + s_aoff[row] + kbase + c*8);
        }
#pragma unroll
        for (int i = 0; i < 4; i++){
            int idx = tid + i*128;
            int row = idx >> 2;
            int c   = idx & 3;
            uint32_t soff = (uint32_t)row*64u + (uint32_t)((c ^ ((row>>1)&3))<<4);
            cpa16(st + OFF_B + soff, B + s_boff[row] + kbase + c*8);
        }
    };

    // prologue: 5 stages in flight (NK >= 16 for both instantiations)
#pragma unroll
    for (int s = 0; s < 5; s++){
        copy_stage(s, s);
        asm volatile("cp.async.commit_group;" ::: "memory");
    }

    float acc[4][8][4];
#pragma unroll
    for (int a = 0; a < 4; a++)
#pragma unroll
        for (int b = 0; b < 8; b++)
#pragma unroll
            for (int c = 0; c < 4; c++) acc[a][b][c] = 0.0f;

    int arow0 = wm*64 + (lane & 15);
    int achk  = lane >> 4;                       // 0/1
    int bgrp  = lane >> 3;                       // 0..3
    int brow0 = wn*64 + (bgrp >> 1)*8 + (lane & 7);
    int bchk  = bgrp & 1;                        // 0/1

    for (int kt = 0; kt < NK; kt++){
        // stage kt complete when pending <= (commits so far) - (kt+1)
        if (kt + 5 <= NK)      asm volatile("cp.async.wait_group 4;" ::: "memory");
        else if (kt + 4 <= NK) asm volatile("cp.async.wait_group 3;" ::: "memory");
        else if (kt + 3 <= NK) asm volatile("cp.async.wait_group 2;" ::: "memory");
        else if (kt + 2 <= NK) asm volatile("cp.async.wait_group 1;" ::: "memory");
        else                   asm volatile("cp.async.wait_group 0;" ::: "memory");
        __syncthreads();

        uint32_t st = sm + (kt % 6)*STAGE_BYTES;
#pragma unroll
        for (int ks = 0; ks < 2; ks++){
            uint32_t ahf[4][4];
#pragma unroll
            for (int mt = 0; mt < 4; mt++){
                int r  = arow0 + mt*16;
                int ch = ks*2 + achk;            // 0..3
                uint32_t sa = (uint32_t)r*64u + (uint32_t)(((ch ^ ((r>>1)&3)) & 3)<<4);
                ldm_x4(ahf[mt], st + OFF_A + sa);
            }
#pragma unroll
            for (int ntp = 0; ntp < 4; ntp++){
                int r  = brow0 + ntp*16;
                int ch = ks*2 + bchk;
                uint32_t sb = (uint32_t)r*64u + (uint32_t)(((ch ^ ((r>>1)&3)) & 3)<<4);
                uint32_t bf4[4];
                ldm_x4(bf4, st + OFF_B + sb);
#pragma unroll
                for (int mt = 0; mt < 4; mt++){
                    mma16816(acc[mt][2*ntp  ], ahf[mt], bf4    );
                    mma16816(acc[mt][2*ntp+1], ahf[mt], bf4 + 2);
                }
            }
        }
        __syncthreads();
        if (kt + 5 < NK){
            copy_stage(kt + 5, (kt + 5) % 6);
            asm volatile("cp.async.commit_group;" ::: "memory");
        }
    }

    // epilogue
    int g   = lane >> 2;
    int tgi = lane & 3;
#pragma unroll
    for (int mt = 0; mt < 4; mt++){
#pragma unroll
        for (int h = 0; h < 2; h++){
            int r = wm*64 + mt*16 + g + h*8;
            int m = m0 + r;
            if (EXPERT && m >= cnt) continue;
            float w = 1.0f;
            size_t rowbase;
            if (EXPERT){
                int p = base + m;
                w = g_pair_w[p];
                rowbase = (size_t)p * DOWND;
            } else {
                rowbase = (size_t)m * HID;
            }
#pragma unroll
            for (int nt = 0; nt < 8; nt++){
                int col = n0 + wn*64 + nt*8 + tgi*2;
                float2 v;
                v.x = (acc[mt][nt][2*h+0] + __ldg(bptr + col    )) * w;
                v.y = (acc[mt][nt][2*h+1] + __ldg(bptr + col + 1)) * w;
                *(float2*)&C[rowbase + col] = v;
            }
        }
    }
}

// ---------------- combine + gelu -> fp16 ----------------
__global__ void k_combine(){
    int idx = blockIdx.x * blockDim.x + threadIdx.x;   // over NTOK*DOWND/4
    int n = idx >> 7;
    int d = idx & 127;
    int p0 = g_tok_pair[2*n], p1 = g_tok_pair[2*n+1];
    float4 v0 = *(const float4*)&g_eo[(size_t)p0*DOWND + 4*d];
    float4 v1 = *(const float4*)&g_eo[(size_t)p1*DOWND + 4*d];
    float g0 = gelu_new(v0.x + v1.x);
    float g1 = gelu_new(v0.y + v1.y);
    float g2 = gelu_new(v0.z + v1.z);
    float g3 = gelu_new(v0.w + v1.w);
    size_t o = (size_t)n*DOWND + 4*d;
    ((__half2*)&g_hh[o])[0] = __floats2half2_rn(g0, g1);
    ((__half2*)&g_hh[o])[1] = __floats2half2_rn(g2, g3);
}

// ---------------- launch ----------------
extern "C" void kernel_launch(void* const* d_in, const int* in_sizes, int n_in,
                              void* d_out, int out_size){
    const float* x      = (const float*)d_in[0];
    const float* gate_w = (const float*)d_in[1];
    const float* down_w = (const float*)d_in[2];
    const float* down_b = (const float*)d_in[3];
    const float* up_w   = (const float*)d_in[4];
    const float* up_b   = (const float*)d_in[5];
    float* out = (float*)d_out;

    // REAL device addresses of __device__ symbols
    void *p_xh, *p_wh, *p_uh, *p_hh, *p_eo;
    cudaGetSymbolAddress(&p_xh, g_xh);
    cudaGetSymbolAddress(&p_wh, g_wh);
    cudaGetSymbolAddress(&p_uh, g_uh);
    cudaGetSymbolAddress(&p_hh, g_hh);
    cudaGetSymbolAddress(&p_eo, g_eo);

    cudaFuncSetAttribute(k_gemm<true,  HID>,   cudaFuncAttributeMaxDynamicSharedMemorySize, GSMEM);
    cudaFuncSetAttribute(k_gemm<false, DOWND>, cudaFuncAttributeMaxDynamicSharedMemorySize, GSMEM);

    k_init<<<1, 32>>>();
    k_gate<<<NTOK/8, 256>>>(x, gate_w, (__half*)p_xh);
    k_prefix<<<1, 1>>>(out + (size_t)NTOK * HID);   // loss scalar after [B,S,HIDDEN]
    k_scatter<<<NTOK/256, 256>>>();

    // weight fp16 conversions
    k_cvt1<<<(NE*DOWND*HID/4 + 255)/256, 256>>>(down_w, (__half*)p_wh, NE*DOWND*HID/4);
    k_cvt1<<<(HID*DOWND/4 + 255)/256, 256>>>(up_w, (__half*)p_uh, HID*DOWND/4);

    // grouped expert GEMM: C[pair, down] = (Xg . We^T + b_e) * w_pair
    dim3 ge(64, DOWND/128, NE);   // 64 m-tiles of 128 covers worst-case skew
    k_gemm<true, HID><<<ge, 128, GSMEM>>>(
        (const __half*)p_xh, (const __half*)p_wh, down_b, (float*)p_eo);

    k_combine<<<(NTOK*DOWND/4)/256, 256>>>();

    // up projection: out = h . up_w^T + up_b
    dim3 gu(NTOK/128, HID/128);
    k_gemm<false, DOWND><<<gu, 128, GSMEM>>>(
        (const __half*)p_hh, (const __half*)p_uh, up_b, out);
}

// round 11
// speedup vs baseline: 4.9939x; 1.0379x over previous
#include <cuda_runtime.h>
#include <cuda_fp16.h>
#include <math.h>
#include <stdint.h>

#define HID   2048
#define DOWND 512
#define NE    16
#define NTOK  8192
#define NPAIR (NTOK*2)

// ---------------- scratch (static device memory; no allocs allowed) ----------------
__device__ float  g_comb[NTOK*DOWND];      // combined expert outputs (fp32, atomic)
__device__ __half g_xh[NTOK*HID];          // x as fp16
__device__ __half g_wh[NE*DOWND*HID];      // down_w fp16
__device__ __half g_uh[HID*DOWND];         // up_w fp16
__device__ __half g_hh[NTOK*DOWND];        // gelu(combined) fp16
__device__ int   g_pair_tok[NPAIR];
__device__ float g_pair_w [NPAIR];
__device__ int   g_ei[NTOK*2];
__device__ float g_wp[NTOK*2];
__device__ int   g_cnt[NE];
__device__ int   g_off[NE];
__device__ int   g_cur[NE];
__device__ float g_sum[NE];

// ---------------- PTX helpers (Ampere-class: valid on compute_103 base) ----------------
__device__ __forceinline__ uint32_t smem_u32(const void* p){
    uint32_t a;
    asm("{ .reg .u64 t; cvta.to.shared.u64 t, %1; cvt.u32.u64 %0, t; }" : "=r"(a) : "l"(p));
    return a;
}
__device__ __forceinline__ void cpa16(uint32_t saddr, const void* g){
    asm volatile("cp.async.cg.shared.global [%0], [%1], 16;" :: "r"(saddr), "l"(g));
}
__device__ __forceinline__ void ldm_x4(uint32_t* r, uint32_t addr){
    asm volatile("ldmatrix.sync.aligned.m8n8.x4.shared.b16 {%0,%1,%2,%3}, [%4];"
        : "=r"(r[0]), "=r"(r[1]), "=r"(r[2]), "=r"(r[3]) : "r"(addr));
}
__device__ __forceinline__ void mma16816(float* c, const uint32_t* a, const uint32_t* b){
    asm volatile("mma.sync.aligned.m16n8k16.row.col.f32.f16.f16.f32 "
        "{%0,%1,%2,%3}, {%4,%5,%6,%7}, {%8,%9}, {%0,%1,%2,%3};"
        : "+f"(c[0]), "+f"(c[1]), "+f"(c[2]), "+f"(c[3])
        : "r"(a[0]), "r"(a[1]), "r"(a[2]), "r"(a[3]), "r"(b[0]), "r"(b[1]));
}

__device__ __forceinline__ float gelu_new(float v){
    float c = v + 0.044715f * v * v * v;
    return 0.5f * v * (1.0f + tanhf(0.7978845608028654f * c));
}

// ---------------- routing kernels ----------------
__global__ void k_init(){
    int t = threadIdx.x;
    if (t < NE){ g_cnt[t] = 0; g_sum[t] = 0.0f; }
}

// zero the combine buffer (graph-safe, deterministic)
__global__ void k_zero(float* __restrict__ c){
    int i = blockIdx.x * blockDim.x + threadIdx.x;
    ((float4*)c)[i] = make_float4(0.f, 0.f, 0.f, 0.f);
}

// warp per token: gate logits + top-2 softmax; ALSO writes x as fp16
__global__ void k_gate(const float* __restrict__ x, const float* __restrict__ gw,
                       __half* __restrict__ xh){
    int w    = threadIdx.x >> 5;
    int lane = threadIdx.x & 31;
    int n = blockIdx.x * 8 + w;
    const float4* xr = (const float4*)(x + (size_t)n * HID);
    const float4* g4 = (const float4*)gw;
    float acc[NE];
#pragma unroll
    for (int e = 0; e < NE; e++) acc[e] = 0.0f;
    for (int i = 0; i < 16; i++){
        int j = lane + 32*i;
        float4 xv = xr[j];
        size_t o = (size_t)n*HID + (size_t)j*4;
        ((__half2*)(xh + o))[0] = __floats2half2_rn(xv.x, xv.y);
        ((__half2*)(xh + o))[1] = __floats2half2_rn(xv.z, xv.w);
#pragma unroll
        for (int e = 0; e < NE; e++){
            float4 gv = g4[e*(HID/4) + j];
            acc[e] += xv.x*gv.x + xv.y*gv.y + xv.z*gv.z + xv.w*gv.w;
        }
    }
#pragma unroll
    for (int e = 0; e < NE; e++){
#pragma unroll
        for (int o = 16; o > 0; o >>= 1)
            acc[e] += __shfl_xor_sync(0xffffffffu, acc[e], o);
    }
    if (lane == 0){
        float v0 = -1e30f, v1 = -1e30f; int i0 = 0, i1 = 0;
#pragma unroll
        for (int e = 0; e < NE; e++){
            float v = acc[e];
            if (v > v0){ v1 = v0; i1 = i0; v0 = v; i0 = e; }
            else if (v > v1){ v1 = v; i1 = e; }
        }
        float ee = expf(v1 - v0);
        float s  = 1.0f + ee;
        float w0 = 1.0f / s, w1 = ee / s;
        g_ei[2*n]   = i0; g_ei[2*n+1] = i1;
        g_wp[2*n]   = w0; g_wp[2*n+1] = w1;
        atomicAdd(&g_cnt[i0], 1);  atomicAdd(&g_cnt[i1], 1);
        atomicAdd(&g_sum[i0], w0); atomicAdd(&g_sum[i1], w1);
    }
}

__global__ void k_prefix(float* __restrict__ loss_out){
    if (threadIdx.x == 0 && blockIdx.x == 0){
        int a = 0; float ls = 0.0f;
        for (int e = 0; e < NE; e++){
            g_off[e] = a; g_cur[e] = a; a += g_cnt[e];
            float t = g_sum[e] / (float)NTOK;
            ls += t * t;
        }
        *loss_out = (float)NE * ls * 0.1f;
    }
}

__global__ void k_scatter(){
    int n = blockIdx.x * blockDim.x + threadIdx.x;
    if (n >= NTOK) return;
#pragma unroll
    for (int s = 0; s < 2; s++){
        int e = g_ei[2*n+s];
        int p = atomicAdd(&g_cur[e], 1);
        g_pair_tok[p] = n;
        g_pair_w [p]  = g_wp[2*n+s];
    }
}

// ---------------- fp32 -> fp16 conversion (weights) ----------------
__global__ void k_cvt1(const float* __restrict__ in, __half* __restrict__ h, int n4){
    int i = blockIdx.x * blockDim.x + threadIdx.x;
    if (i >= n4) return;
    float4 v = ((const float4*)in)[i];
    ((__half2*)h)[2*i]   = __floats2half2_rn(v.x, v.y);
    ((__half2*)h)[2*i+1] = __floats2half2_rn(v.z, v.w);
}

// ---------------- warp-MMA GEMM (single fp16, fp32 accum) ----------------
// Block 128x128, BK=64, 4 warps (2x2), warp tile 64x64. 3-stage cp.async pipeline.
// A/B rows: 64 fp16 = 128B = 8 x 16B chunks, XOR swizzle (c ^ (row&7)).
// Stage = A 16KB + B 16KB = 32KB; 3 stages = 96KB -> 2 CTAs/SM.
#define STAGE_BYTES 32768
#define OFF_A 0
#define OFF_B 16384
#define GSMEM  (3*STAGE_BYTES)

template<bool EXPERT, int KDIM>
__global__ void __launch_bounds__(128, 2)
k_gemm(const __half* __restrict__ A, const __half* __restrict__ B,
       const float* __restrict__ bias, float* __restrict__ C)
{
    int e   = EXPERT ? blockIdx.z : 0;
    int cnt = EXPERT ? g_cnt[e] : NTOK;
    int m0  = blockIdx.x * 128;
    if (m0 >= cnt) return;
    int base = EXPERT ? g_off[e] : 0;
    int n0   = blockIdx.y * 128;
    const float* bptr = EXPERT ? bias + e*DOWND : bias;

    extern __shared__ char smem[];
    uint32_t sm = smem_u32(smem);
    __shared__ int s_aoff[128];
    __shared__ int s_atok[128];
    __shared__ int s_boff[128];

    int tid  = threadIdx.x;
    int lane = tid & 31;
    int wid  = tid >> 5;
    int wm   = wid >> 1;      // 0..1 (M)
    int wn   = wid & 1;       // 0..1 (N)

    {
        int m = m0 + tid;
        int ar;
        if (EXPERT){
            ar = g_pair_tok[base + ((m < cnt) ? m : 0)];
            s_atok[tid] = ar;
        } else {
            ar = m;
        }
        s_aoff[tid] = ar * KDIM;
        int bn = (EXPERT ? e*DOWND : 0) + n0 + tid;
        s_boff[tid] = bn * KDIM;
    }
    __syncthreads();

    const int NK = KDIM / 64;   // 32 expert, 8 up

    auto copy_stage = [&](int kt, int buf){
        uint32_t st = sm + buf*STAGE_BYTES;
        int kbase = kt*64;
        int c  = tid & 7;
        int rb = tid >> 3;           // 0..15
#pragma unroll
        for (int i = 0; i < 8; i++){
            int row = rb + i*16;
            uint32_t soff = (uint32_t)row*128u + (uint32_t)((c ^ (row & 7))<<4);
            cpa16(st + OFF_A + soff, A + s_aoff[row] + kbase + c*8);
        }
#pragma unroll
        for (int i = 0; i < 8; i++){
            int row = rb + i*16;
            uint32_t soff = (uint32_t)row*128u + (uint32_t)((c ^ (row & 7))<<4);
            cpa16(st + OFF_B + soff, B + s_boff[row] + kbase + c*8);
        }
    };

    copy_stage(0, 0);
    asm volatile("cp.async.commit_group;" ::: "memory");
    copy_stage(1, 1);
    asm volatile("cp.async.commit_group;" ::: "memory");
    copy_stage(2, 2);
    asm volatile("cp.async.commit_group;" ::: "memory");

    float acc[4][8][4];
#pragma unroll
    for (int a = 0; a < 4; a++)
#pragma unroll
        for (int b = 0; b < 8; b++)
#pragma unroll
            for (int c = 0; c < 4; c++) acc[a][b][c] = 0.0f;

    int arow0 = wm*64 + (lane & 15);
    int achk  = lane >> 4;                       // 0/1
    int bgrp  = lane >> 3;                       // 0..3
    int brow0 = wn*64 + (bgrp >> 1)*8 + (lane & 7);
    int bchk  = bgrp & 1;                        // 0/1

    for (int kt = 0; kt < NK; kt++){
        if (kt + 2 < NK)      asm volatile("cp.async.wait_group 2;" ::: "memory");
        else if (kt + 1 < NK) asm volatile("cp.async.wait_group 1;" ::: "memory");
        else                  asm volatile("cp.async.wait_group 0;" ::: "memory");
        __syncthreads();

        uint32_t st = sm + (kt % 3)*STAGE_BYTES;
#pragma unroll
        for (int ks = 0; ks < 4; ks++){
            uint32_t ahf[4][4];
#pragma unroll
            for (int mt = 0; mt < 4; mt++){
                int r  = arow0 + mt*16;
                int ch = ks*2 + achk;            // 0..7
                uint32_t sa = (uint32_t)r*128u + (uint32_t)(((ch ^ (r & 7)) & 7)<<4);
                ldm_x4(ahf[mt], st + OFF_A + sa);
            }
#pragma unroll
            for (int ntp = 0; ntp < 4; ntp++){
                int r  = brow0 + ntp*16;
                int ch = ks*2 + bchk;
                uint32_t sb = (uint32_t)r*128u + (uint32_t)(((ch ^ (r & 7)) & 7)<<4);
                uint32_t bf4[4];
                ldm_x4(bf4, st + OFF_B + sb);
#pragma unroll
                for (int mt = 0; mt < 4; mt++){
                    mma16816(acc[mt][2*ntp  ], ahf[mt], bf4    );
                    mma16816(acc[mt][2*ntp+1], ahf[mt], bf4 + 2);
                }
            }
        }
        __syncthreads();
        if (kt + 3 < NK){
            copy_stage(kt + 3, (kt + 3) % 3);
            asm volatile("cp.async.commit_group;" ::: "memory");
        }
    }

    // epilogue
    int g   = lane >> 2;
    int tgi = lane & 3;
#pragma unroll
    for (int mt = 0; mt < 4; mt++){
#pragma unroll
        for (int h = 0; h < 2; h++){
            int r = wm*64 + mt*16 + g + h*8;
            int m = m0 + r;
            if (EXPERT && m >= cnt) continue;
            if (EXPERT){
                // scatter-add (w * (acc + bias)) into combined token buffer.
                // Each element receives exactly 2 contributions (top-2 experts)
                // onto a zeroed buffer -> order-independent fp32 result.
                float w = g_pair_w[base + m];
                size_t rowbase = (size_t)s_atok[r] * DOWND;
#pragma unroll
                for (int nt = 0; nt < 8; nt++){
                    int col = n0 + wn*64 + nt*8 + tgi*2;
                    atomicAdd(&C[rowbase + col    ], (acc[mt][nt][2*h+0] + __ldg(bptr + col    )) * w);
                    atomicAdd(&C[rowbase + col + 1], (acc[mt][nt][2*h+1] + __ldg(bptr + col + 1)) * w);
                }
            } else {
                size_t rowbase = (size_t)m * HID;
#pragma unroll
                for (int nt = 0; nt < 8; nt++){
                    int col = n0 + wn*64 + nt*8 + tgi*2;
                    float2 v;
                    v.x = acc[mt][nt][2*h+0] + __ldg(bptr + col    );
                    v.y = acc[mt][nt][2*h+1] + __ldg(bptr + col + 1);
                    *(float2*)&C[rowbase + col] = v;
                }
            }
        }
    }
}

// ---------------- gelu over combined buffer -> fp16 ----------------
__global__ void k_combine(const float* __restrict__ comb, __half* __restrict__ hh){
    int i = blockIdx.x * blockDim.x + threadIdx.x;   // over NTOK*DOWND/4
    float4 v = ((const float4*)comb)[i];
    float g0 = gelu_new(v.x);
    float g1 = gelu_new(v.y);
    float g2 = gelu_new(v.z);
    float g3 = gelu_new(v.w);
    ((__half2*)hh)[2*i]   = __floats2half2_rn(g0, g1);
    ((__half2*)hh)[2*i+1] = __floats2half2_rn(g2, g3);
}

// ---------------- launch ----------------
extern "C" void kernel_launch(void* const* d_in, const int* in_sizes, int n_in,
                              void* d_out, int out_size){
    const float* x      = (const float*)d_in[0];
    const float* gate_w = (const float*)d_in[1];
    const float* down_w = (const float*)d_in[2];
    const float* down_b = (const float*)d_in[3];
    const float* up_w   = (const float*)d_in[4];
    const float* up_b   = (const float*)d_in[5];
    float* out = (float*)d_out;

    // REAL device addresses of __device__ symbols
    void *p_xh, *p_wh, *p_uh, *p_hh, *p_comb;
    cudaGetSymbolAddress(&p_xh,   g_xh);
    cudaGetSymbolAddress(&p_wh,   g_wh);
    cudaGetSymbolAddress(&p_uh,   g_uh);
    cudaGetSymbolAddress(&p_hh,   g_hh);
    cudaGetSymbolAddress(&p_comb, g_comb);

    cudaFuncSetAttribute(k_gemm<true,  HID>,   cudaFuncAttributeMaxDynamicSharedMemorySize, GSMEM);
    cudaFuncSetAttribute(k_gemm<false, DOWND>, cudaFuncAttributeMaxDynamicSharedMemorySize, GSMEM);

    k_init<<<1, 32>>>();
    k_zero<<<(NTOK*DOWND/4)/256, 256>>>((float*)p_comb);
    k_gate<<<NTOK/8, 256>>>(x, gate_w, (__half*)p_xh);
    k_prefix<<<1, 1>>>(out + (size_t)NTOK * HID);   // loss scalar after [B,S,HIDDEN]
    k_scatter<<<NTOK/256, 256>>>();

    // weight fp16 conversions
    k_cvt1<<<(NE*DOWND*HID/4 + 255)/256, 256>>>(down_w, (__half*)p_wh, NE*DOWND*HID/4);
    k_cvt1<<<(HID*DOWND/4 + 255)/256, 256>>>(up_w, (__half*)p_uh, HID*DOWND/4);

    // grouped expert GEMM with fused scatter-add combine
    dim3 ge(64, DOWND/128, NE);   // 64 m-tiles of 128 covers worst-case skew
    k_gemm<true, HID><<<ge, 128, GSMEM>>>(
        (const __half*)p_xh, (const __half*)p_wh, down_b, (float*)p_comb);

    k_combine<<<(NTOK*DOWND/4)/256, 256>>>((const float*)p_comb, (__half*)p_hh);

    // up projection: out = h . up_w^T + up_b
    dim3 gu(NTOK/128, HID/128);
    k_gemm<false, DOWND><<<gu, 128, GSMEM>>>(
        (const __half*)p_hh, (const __half*)p_uh, up_b, out);
}

// round 12
// speedup vs baseline: 5.2722x; 1.0557x over previous
#include <cuda_runtime.h>
#include <cuda_fp16.h>
#include <math.h>
#include <stdint.h>

#define HID   2048
#define DOWND 512
#define NE    16
#define NTOK  8192
#define NPAIR (NTOK*2)

// ---------------- scratch (static device memory; no allocs allowed) ----------------
__device__ float  g_comb[NTOK*DOWND];      // combined expert outputs (fp32, atomic)
__device__ __half g_xh[NTOK*HID];          // x as fp16
__device__ __half g_wh[NE*DOWND*HID];      // down_w fp16
__device__ __half g_uh[HID*DOWND];         // up_w fp16
__device__ __half g_hh[NTOK*DOWND];        // gelu(combined) fp16
__device__ int   g_pair_tok[NPAIR];
__device__ float g_pair_w [NPAIR];
__device__ int   g_ei[NTOK*2];
__device__ float g_wp[NTOK*2];
__device__ int   g_cnt[NE];
__device__ int   g_off[NE];
__device__ int   g_cur[NE];
__device__ float g_sum[NE];

// ---------------- PTX helpers (Ampere-class: valid on compute_103 base) ----------------
__device__ __forceinline__ uint32_t smem_u32(const void* p){
    uint32_t a;
    asm("{ .reg .u64 t; cvta.to.shared.u64 t, %1; cvt.u32.u64 %0, t; }" : "=r"(a) : "l"(p));
    return a;
}
__device__ __forceinline__ void cpa16(uint32_t saddr, const void* g){
    asm volatile("cp.async.cg.shared.global [%0], [%1], 16;" :: "r"(saddr), "l"(g));
}
__device__ __forceinline__ void ldm_x4(uint32_t* r, uint32_t addr){
    asm volatile("ldmatrix.sync.aligned.m8n8.x4.shared.b16 {%0,%1,%2,%3}, [%4];"
        : "=r"(r[0]), "=r"(r[1]), "=r"(r[2]), "=r"(r[3]) : "r"(addr));
}
__device__ __forceinline__ void mma16816(float* c, const uint32_t* a, const uint32_t* b){
    asm volatile("mma.sync.aligned.m16n8k16.row.col.f32.f16.f16.f32 "
        "{%0,%1,%2,%3}, {%4,%5,%6,%7}, {%8,%9}, {%0,%1,%2,%3};"
        : "+f"(c[0]), "+f"(c[1]), "+f"(c[2]), "+f"(c[3])
        : "r"(a[0]), "r"(a[1]), "r"(a[2]), "r"(a[3]), "r"(b[0]), "r"(b[1]));
}

__device__ __forceinline__ float gelu_new(float v){
    float c = v + 0.044715f * v * v * v;
    return 0.5f * v * (1.0f + tanhf(0.7978845608028654f * c));
}

// ---------------- init + zero (merged) ----------------
__global__ void k_zero(float* __restrict__ c){
    int i = blockIdx.x * blockDim.x + threadIdx.x;
    ((float4*)c)[i] = make_float4(0.f, 0.f, 0.f, 0.f);
    if (blockIdx.x == 0 && threadIdx.x < NE){
        g_cnt[threadIdx.x] = 0; g_sum[threadIdx.x] = 0.0f;
    }
}

// ---------------- gate: 4 tokens per warp (gate_w L1 traffic /4) ----------------
__global__ void k_gate(const float* __restrict__ x, const float* __restrict__ gw,
                       __half* __restrict__ xh){
    int warp = threadIdx.x >> 5;
    int lane = threadIdx.x & 31;
    int n0 = (blockIdx.x * 8 + warp) * 4;      // 4 tokens per warp
    const float4* x4 = (const float4*)x;
    const float4* g4 = (const float4*)gw;
    float acc[4][NE];
#pragma unroll
    for (int t = 0; t < 4; t++)
#pragma unroll
        for (int e = 0; e < NE; e++) acc[t][e] = 0.0f;

    for (int i = 0; i < 16; i++){
        int j = lane + 32*i;
        float4 xv[4];
#pragma unroll
        for (int t = 0; t < 4; t++){
            xv[t] = x4[(size_t)(n0+t)*(HID/4) + j];
            size_t o = (size_t)(n0+t)*HID + (size_t)j*4;
            ((__half2*)(xh + o))[0] = __floats2half2_rn(xv[t].x, xv[t].y);
            ((__half2*)(xh + o))[1] = __floats2half2_rn(xv[t].z, xv[t].w);
        }
#pragma unroll
        for (int e = 0; e < NE; e++){
            float4 gv = g4[e*(HID/4) + j];
#pragma unroll
            for (int t = 0; t < 4; t++)
                acc[t][e] += xv[t].x*gv.x + xv[t].y*gv.y + xv[t].z*gv.z + xv[t].w*gv.w;
        }
    }
#pragma unroll
    for (int t = 0; t < 4; t++)
#pragma unroll
        for (int e = 0; e < NE; e++){
#pragma unroll
            for (int o = 16; o > 0; o >>= 1)
                acc[t][e] += __shfl_xor_sync(0xffffffffu, acc[t][e], o);
        }
    if (lane == 0){
#pragma unroll
        for (int t = 0; t < 4; t++){
            int n = n0 + t;
            float v0 = -1e30f, v1 = -1e30f; int i0 = 0, i1 = 0;
#pragma unroll
            for (int e = 0; e < NE; e++){
                float v = acc[t][e];
                if (v > v0){ v1 = v0; i1 = i0; v0 = v; i0 = e; }
                else if (v > v1){ v1 = v; i1 = e; }
            }
            float ee = expf(v1 - v0);
            float s  = 1.0f + ee;
            float w0 = 1.0f / s, w1 = ee / s;
            g_ei[2*n]   = i0; g_ei[2*n+1] = i1;
            g_wp[2*n]   = w0; g_wp[2*n+1] = w1;
            atomicAdd(&g_cnt[i0], 1);  atomicAdd(&g_cnt[i1], 1);
            atomicAdd(&g_sum[i0], w0); atomicAdd(&g_sum[i1], w1);
        }
    }
}

__global__ void k_prefix(float* __restrict__ loss_out){
    if (threadIdx.x == 0 && blockIdx.x == 0){
        int a = 0; float ls = 0.0f;
        for (int e = 0; e < NE; e++){
            g_off[e] = a; g_cur[e] = a; a += g_cnt[e];
            float t = g_sum[e] / (float)NTOK;
            ls += t * t;
        }
        *loss_out = (float)NE * ls * 0.1f;
    }
}

__global__ void k_scatter(){
    int n = blockIdx.x * blockDim.x + threadIdx.x;
    if (n >= NTOK) return;
#pragma unroll
    for (int s = 0; s < 2; s++){
        int e = g_ei[2*n+s];
        int p = atomicAdd(&g_cur[e], 1);
        g_pair_tok[p] = n;
        g_pair_w [p]  = g_wp[2*n+s];
    }
}

// ---------------- fp32 -> fp16 conversion (both weight tensors, one kernel) ----------------
#define N4_DW (NE*DOWND*HID/4)
#define N4_UW (HID*DOWND/4)
__global__ void k_cvt1(const float* __restrict__ dw, __half* __restrict__ wh,
                       const float* __restrict__ uw, __half* __restrict__ uh){
    int i = blockIdx.x * blockDim.x + threadIdx.x;
    const float* in; __half* h; int idx;
    if (i < N4_DW){ in = dw; h = wh; idx = i; }
    else if (i < N4_DW + N4_UW){ in = uw; h = uh; idx = i - N4_DW; }
    else return;
    float4 v = ((const float4*)in)[idx];
    ((__half2*)h)[2*idx]   = __floats2half2_rn(v.x, v.y);
    ((__half2*)h)[2*idx+1] = __floats2half2_rn(v.z, v.w);
}

// ---------------- warp-MMA GEMM (single fp16, fp32 accum) ----------------
// Block 128x128, BK=64, 4 warps (2x2), warp tile 64x64. 3-stage cp.async pipeline,
// plus intra-kt ldmatrix fragment double-buffering (prefetch ks+1 during ks MMAs).
#define STAGE_BYTES 32768
#define OFF_A 0
#define OFF_B 16384
#define GSMEM  (3*STAGE_BYTES)

template<bool EXPERT, int KDIM>
__global__ void __launch_bounds__(128, 2)
k_gemm(const __half* __restrict__ A, const __half* __restrict__ B,
       const float* __restrict__ bias, float* __restrict__ C)
{
    int e   = EXPERT ? blockIdx.z : 0;
    int cnt = EXPERT ? g_cnt[e] : NTOK;
    int m0  = blockIdx.x * 128;
    if (m0 >= cnt) return;
    int base = EXPERT ? g_off[e] : 0;
    int n0   = blockIdx.y * 128;
    const float* bptr = EXPERT ? bias + e*DOWND : bias;

    extern __shared__ char smem[];
    uint32_t sm = smem_u32(smem);
    __shared__ int s_aoff[128];
    __shared__ int s_atok[128];
    __shared__ int s_boff[128];

    int tid  = threadIdx.x;
    int lane = tid & 31;
    int wid  = tid >> 5;
    int wm   = wid >> 1;      // 0..1 (M)
    int wn   = wid & 1;       // 0..1 (N)

    {
        int m = m0 + tid;
        int ar;
        if (EXPERT){
            ar = g_pair_tok[base + ((m < cnt) ? m : 0)];
            s_atok[tid] = ar;
        } else {
            ar = m;
        }
        s_aoff[tid] = ar * KDIM;
        int bn = (EXPERT ? e*DOWND : 0) + n0 + tid;
        s_boff[tid] = bn * KDIM;
    }
    __syncthreads();

    const int NK = KDIM / 64;   // 32 expert, 8 up

    auto copy_stage = [&](int kt, int buf){
        uint32_t st = sm + buf*STAGE_BYTES;
        int kbase = kt*64;
        int c  = tid & 7;
        int rb = tid >> 3;           // 0..15
#pragma unroll
        for (int i = 0; i < 8; i++){
            int row = rb + i*16;
            uint32_t soff = (uint32_t)row*128u + (uint32_t)((c ^ (row & 7))<<4);
            cpa16(st + OFF_A + soff, A + s_aoff[row] + kbase + c*8);
        }
#pragma unroll
        for (int i = 0; i < 8; i++){
            int row = rb + i*16;
            uint32_t soff = (uint32_t)row*128u + (uint32_t)((c ^ (row & 7))<<4);
            cpa16(st + OFF_B + soff, B + s_boff[row] + kbase + c*8);
        }
    };

    copy_stage(0, 0);
    asm volatile("cp.async.commit_group;" ::: "memory");
    copy_stage(1, 1);
    asm volatile("cp.async.commit_group;" ::: "memory");
    copy_stage(2, 2);
    asm volatile("cp.async.commit_group;" ::: "memory");

    float acc[4][8][4];
#pragma unroll
    for (int a = 0; a < 4; a++)
#pragma unroll
        for (int b = 0; b < 8; b++)
#pragma unroll
            for (int c = 0; c < 4; c++) acc[a][b][c] = 0.0f;

    int arow0 = wm*64 + (lane & 15);
    int achk  = lane >> 4;                       // 0/1
    int bgrp  = lane >> 3;                       // 0..3
    int brow0 = wn*64 + (bgrp >> 1)*8 + (lane & 7);
    int bchk  = bgrp & 1;                        // 0/1

    uint32_t fa[2][4][4], fb[2][4][4];

    auto load_frags = [&](int ks, uint32_t st, uint32_t (*fA)[4], uint32_t (*fB)[4]){
#pragma unroll
        for (int mt = 0; mt < 4; mt++){
            int r  = arow0 + mt*16;
            int ch = ks*2 + achk;
            uint32_t sa = (uint32_t)r*128u + (uint32_t)(((ch ^ (r & 7)) & 7)<<4);
            ldm_x4(fA[mt], st + OFF_A + sa);
        }
#pragma unroll
        for (int ntp = 0; ntp < 4; ntp++){
            int r  = brow0 + ntp*16;
            int ch = ks*2 + bchk;
            uint32_t sb = (uint32_t)r*128u + (uint32_t)(((ch ^ (r & 7)) & 7)<<4);
            ldm_x4(fB[ntp], st + OFF_B + sb);
        }
    };

    for (int kt = 0; kt < NK; kt++){
        if (kt + 2 < NK)      asm volatile("cp.async.wait_group 2;" ::: "memory");
        else if (kt + 1 < NK) asm volatile("cp.async.wait_group 1;" ::: "memory");
        else                  asm volatile("cp.async.wait_group 0;" ::: "memory");
        __syncthreads();

        uint32_t st = sm + (kt % 3)*STAGE_BYTES;
        load_frags(0, st, fa[0], fb[0]);
#pragma unroll
        for (int ks = 0; ks < 4; ks++){
            int cur = ks & 1;
            if (ks < 3) load_frags(ks + 1, st, fa[cur^1], fb[cur^1]);
#pragma unroll
            for (int ntp = 0; ntp < 4; ntp++){
#pragma unroll
                for (int mt = 0; mt < 4; mt++){
                    mma16816(acc[mt][2*ntp  ], fa[cur][mt], fb[cur][ntp]    );
                    mma16816(acc[mt][2*ntp+1], fa[cur][mt], fb[cur][ntp] + 2);
                }
            }
        }
        __syncthreads();
        if (kt + 3 < NK){
            copy_stage(kt + 3, (kt + 3) % 3);
            asm volatile("cp.async.commit_group;" ::: "memory");
        }
    }

    // epilogue
    int g   = lane >> 2;
    int tgi = lane & 3;
#pragma unroll
    for (int mt = 0; mt < 4; mt++){
#pragma unroll
        for (int h = 0; h < 2; h++){
            int r = wm*64 + mt*16 + g + h*8;
            int m = m0 + r;
            if (EXPERT && m >= cnt) continue;
            if (EXPERT){
                // scatter-add (w * (acc + bias)) into combined token buffer.
                // Exactly 2 contributions per element onto a zeroed buffer ->
                // order-independent fp32 result.
                float w = g_pair_w[base + m];
                size_t rowbase = (size_t)s_atok[r] * DOWND;
#pragma unroll
                for (int nt = 0; nt < 8; nt++){
                    int col = n0 + wn*64 + nt*8 + tgi*2;
                    float2 v;
                    v.x = (acc[mt][nt][2*h+0] + __ldg(bptr + col    )) * w;
                    v.y = (acc[mt][nt][2*h+1] + __ldg(bptr + col + 1)) * w;
                    atomicAdd((float2*)&C[rowbase + col], v);
                }
            } else {
                size_t rowbase = (size_t)m * HID;
#pragma unroll
                for (int nt = 0; nt < 8; nt++){
                    int col = n0 + wn*64 + nt*8 + tgi*2;
                    float2 v;
                    v.x = acc[mt][nt][2*h+0] + __ldg(bptr + col    );
                    v.y = acc[mt][nt][2*h+1] + __ldg(bptr + col + 1);
                    *(float2*)&C[rowbase + col] = v;
                }
            }
        }
    }
}

// ---------------- gelu over combined buffer -> fp16 ----------------
__global__ void k_combine(const float* __restrict__ comb, __half* __restrict__ hh){
    int i = blockIdx.x * blockDim.x + threadIdx.x;   // over NTOK*DOWND/4
    float4 v = ((const float4*)comb)[i];
    float g0 = gelu_new(v.x);
    float g1 = gelu_new(v.y);
    float g2 = gelu_new(v.z);
    float g3 = gelu_new(v.w);
    ((__half2*)hh)[2*i]   = __floats2half2_rn(g0, g1);
    ((__half2*)hh)[2*i+1] = __floats2half2_rn(g2, g3);
}

// ---------------- launch ----------------
extern "C" void kernel_launch(void* const* d_in, const int* in_sizes, int n_in,
                              void* d_out, int out_size){
    const float* x      = (const float*)d_in[0];
    const float* gate_w = (const float*)d_in[1];
    const float* down_w = (const float*)d_in[2];
    const float* down_b = (const float*)d_in[3];
    const float* up_w   = (const float*)d_in[4];
    const float* up_b   = (const float*)d_in[5];
    float* out = (float*)d_out;

    // REAL device addresses of __device__ symbols
    void *p_xh, *p_wh, *p_uh, *p_hh, *p_comb;
    cudaGetSymbolAddress(&p_xh,   g_xh);
    cudaGetSymbolAddress(&p_wh,   g_wh);
    cudaGetSymbolAddress(&p_uh,   g_uh);
    cudaGetSymbolAddress(&p_hh,   g_hh);
    cudaGetSymbolAddress(&p_comb, g_comb);

    cudaFuncSetAttribute(k_gemm<true,  HID>,   cudaFuncAttributeMaxDynamicSharedMemorySize, GSMEM);
    cudaFuncSetAttribute(k_gemm<false, DOWND>, cudaFuncAttributeMaxDynamicSharedMemorySize, GSMEM);

    k_zero<<<(NTOK*DOWND/4)/256, 256>>>((float*)p_comb);       // zero + routing init
    k_gate<<<NTOK/32, 256>>>(x, gate_w, (__half*)p_xh);
    k_prefix<<<1, 1>>>(out + (size_t)NTOK * HID);   // loss scalar after [B,S,HIDDEN]
    k_scatter<<<NTOK/256, 256>>>();

    // weight fp16 conversions (both tensors in one launch)
    k_cvt1<<<(N4_DW + N4_UW + 255)/256, 256>>>(down_w, (__half*)p_wh, up_w, (__half*)p_uh);

    // grouped expert GEMM with fused scatter-add combine
    dim3 ge(64, DOWND/128, NE);   // 64 m-tiles of 128 covers worst-case skew
    k_gemm<true, HID><<<ge, 128, GSMEM>>>(
        (const __half*)p_xh, (const __half*)p_wh, down_b, (float*)p_comb);

    k_combine<<<(NTOK*DOWND/4)/256, 256>>>((const float*)p_comb, (__half*)p_hh);

    // up projection: out = h . up_w^T + up_b
    dim3 gu(NTOK/128, HID/128);
    k_gemm<false, DOWND><<<gu, 128, GSMEM>>>(
        (const __half*)p_hh, (const __half*)p_uh, up_b, out);
}